// round 13
// baseline (speedup 1.0000x reference)
#include <cuda_runtime.h>
#include <cuda_bf16.h>
#include <math.h>
#include <stdint.h>

// ---------------------------------------------------------------------------
// MiniGPT forward. B=2 T=2048 D=256 H=4 DK=64 DFF=1024 L=4 V=32000
// GEMMs: mma.sync bf16x3. qkv/w1/logits TM=64, fc/w2 TM=32.
// Attention: HMMA flash, split-KV x8, FMA-polynomial exp2 in softmax
// (MUFU port was the per-warp critical path; FMA pipe is idle).
// ---------------------------------------------------------------------------

#define Tn    2048
#define Bn    2
#define Dn    256
#define Mrows 4096
#define NSPLIT 8

// fp32 scratch
__device__ float g_x[Mrows * Dn];
__device__ float g_tmp[Mrows * Dn];

// attention split-KV partials
__device__ float g_attp[NSPLIT][Mrows * Dn];
__device__ float g_pm[NSPLIT][Mrows * 4];
__device__ float g_pl[NSPLIT][Mrows * 4];

// bf16 hi/lo activations, qkv, MLP hidden
__device__ __nv_bfloat16 g_acth[Mrows * Dn],  g_actl[Mrows * Dn];
__device__ __nv_bfloat16 g_qkvh[Mrows * 768], g_qkvl[Mrows * 768];
__device__ __nv_bfloat16 g_hh[Mrows * 1024],  g_hl[Mrows * 1024];

// bf16 hi/lo weights
__device__ __nv_bfloat16 g_wqkv_h[4 * 768 * 256],  g_wqkv_l[4 * 768 * 256];
__device__ __nv_bfloat16 g_wfc_h [4 * 256 * 256],  g_wfc_l [4 * 256 * 256];
__device__ __nv_bfloat16 g_w1_h  [4 * 1024 * 256], g_w1_l  [4 * 1024 * 256];
__device__ __nv_bfloat16 g_w2_h  [4 * 256 * 1024], g_w2_l  [4 * 256 * 1024];
__device__ __nv_bfloat16 g_wout_h[32000 * 256],    g_wout_l[32000 * 256];

// ---------------------------------------------------------------------------
// PTX helpers
// ---------------------------------------------------------------------------
__device__ __forceinline__ uint32_t smem_to_u32(const void* p) {
    uint32_t a;
    asm("{ .reg .u64 t; cvta.to.shared.u64 t, %1; cvt.u32.u64 %0, t; }"
        : "=r"(a) : "l"(p));
    return a;
}
__device__ __forceinline__ void ldsm4(uint32_t* r, uint32_t addr) {
    asm volatile("ldmatrix.sync.aligned.m8n8.x4.shared.b16 {%0,%1,%2,%3}, [%4];"
                 : "=r"(r[0]), "=r"(r[1]), "=r"(r[2]), "=r"(r[3]) : "r"(addr));
}
__device__ __forceinline__ void ldsm4t(uint32_t* r, uint32_t addr) {
    asm volatile("ldmatrix.sync.aligned.m8n8.x4.trans.shared.b16 {%0,%1,%2,%3}, [%4];"
                 : "=r"(r[0]), "=r"(r[1]), "=r"(r[2]), "=r"(r[3]) : "r"(addr));
}
__device__ __forceinline__ void mma16816(float* d, const uint32_t* a,
                                         uint32_t b0, uint32_t b1) {
    asm volatile(
        "mma.sync.aligned.m16n8k16.row.col.f32.bf16.bf16.f32 "
        "{%0,%1,%2,%3}, {%4,%5,%6,%7}, {%8,%9}, {%0,%1,%2,%3};"
        : "+f"(d[0]), "+f"(d[1]), "+f"(d[2]), "+f"(d[3])
        : "r"(a[0]), "r"(a[1]), "r"(a[2]), "r"(a[3]), "r"(b0), "r"(b1));
}
__device__ __forceinline__ float ex2f(float x) {
    float y;
    asm("ex2.approx.f32 %0, %1;" : "=f"(y) : "f"(x));
    return y;
}
// FMA-pipe exp2 (round + degree-6 poly + exponent splice). Max rel err ~1e-7.
// Used in the attention softmax where the MUFU port is the warp critical path.
__device__ __forceinline__ float exp2_fma(float x) {
    x = fmaxf(x, -100.f);
    float fi;
    asm("cvt.rni.f32.f32 %0, %1;" : "=f"(fi) : "f"(x));
    float f = x - fi;
    float p = 1.53533618831950e-4f;
    p = fmaf(p, f, 1.33988744026657e-3f);
    p = fmaf(p, f, 9.61843735767464e-3f);
    p = fmaf(p, f, 5.55033247116281e-2f);
    p = fmaf(p, f, 2.40226479136301e-1f);
    p = fmaf(p, f, 6.93147202855042e-1f);
    p = fmaf(p, f, 1.0f);
    return __int_as_float(__float_as_int(p) + ((int)fi << 23));
}
#define CP_ASYNC16(dst, src) \
    asm volatile("cp.async.cg.shared.global [%0], [%1], 16;" \
                 :: "r"(dst), "l"(src) : "memory")
#define CP_COMMIT()  asm volatile("cp.async.commit_group;" ::: "memory")
#define CP_WAIT0()   asm volatile("cp.async.wait_group 0;" ::: "memory")

__device__ __forceinline__ void split1(float v, __nv_bfloat16& h, __nv_bfloat16& l) {
    h = __float2bfloat16(v);
    l = __float2bfloat16(v - __bfloat162float(h));
}

// ---------------------------------------------------------------------------
// Fused weight split
// ---------------------------------------------------------------------------
__global__ void split_weights(const float* __restrict__ qkv_w,
                              const float* __restrict__ fc_w,
                              const float* __restrict__ w1,
                              const float* __restrict__ w2,
                              const float* __restrict__ out_w)
{
    const int c0 = 196608, c1 = c0 + 65536, c2 = c1 + 262144,
              c3 = c2 + 262144, c4 = c3 + 2048000;
    int stride = gridDim.x * blockDim.x;
    for (int idx = blockIdx.x * blockDim.x + threadIdx.x; idx < c4; idx += stride) {
        const float* src; __nv_bfloat16 *dh, *dl; int li;
        if (idx < c0)      { src = qkv_w; dh = g_wqkv_h; dl = g_wqkv_l; li = idx; }
        else if (idx < c1) { src = fc_w;  dh = g_wfc_h;  dl = g_wfc_l;  li = idx - c0; }
        else if (idx < c2) { src = w1;    dh = g_w1_h;   dl = g_w1_l;   li = idx - c1; }
        else if (idx < c3) { src = w2;    dh = g_w2_h;   dl = g_w2_l;   li = idx - c2; }
        else               { src = out_w; dh = g_wout_h; dl = g_wout_l; li = idx - c3; }
        float4 v = ((const float4*)src)[li];
        __nv_bfloat16 h0, h1, h2, h3, l0, l1, l2, l3;
        split1(v.x, h0, l0); split1(v.y, h1, l1);
        split1(v.z, h2, l2); split1(v.w, h3, l3);
        ((__nv_bfloat162*)dh)[li * 2 + 0] = __nv_bfloat162(h0, h1);
        ((__nv_bfloat162*)dh)[li * 2 + 1] = __nv_bfloat162(h2, h3);
        ((__nv_bfloat162*)dl)[li * 2 + 0] = __nv_bfloat162(l0, l1);
        ((__nv_bfloat162*)dl)[li * 2 + 1] = __nv_bfloat162(l2, l3);
    }
}

// ---------------------------------------------------------------------------
// mma.sync bf16x3 GEMM. TM in {64, 32}, TN = 128. (unchanged from R12)
// ---------------------------------------------------------------------------
#define GSMEM64  (2 * 49152)
#define GSMEM32  (2 * 40960)

template<int TM, int N, int K, int RELU, int WSPLIT>
__device__ __forceinline__ void gemm_body(
    const __nv_bfloat16* __restrict__ Ah, const __nv_bfloat16* __restrict__ Al,
    const __nv_bfloat16* __restrict__ Bh, const __nv_bfloat16* __restrict__ Bl,
    const float* __restrict__ bias, float* __restrict__ C,
    __nv_bfloat16* __restrict__ Ch, __nv_bfloat16* __restrict__ Cl)
{
    extern __shared__ char smem[];
    const uint32_t sb = smem_to_u32(smem);
    const int tid  = threadIdx.x;
    const int wid  = tid >> 5;
    const int lane = tid & 31;
    const int m0   = blockIdx.y * TM;
    const int n0   = blockIdx.x << 7;
    constexpr int NST   = K / 64;
    constexpr int STAGE = (TM == 64) ? 49152 : 40960;
    constexpr int AOFF  = (TM == 64) ? 8192 : 4096;
    constexpr int BOFF  = (TM == 64) ? 16384 : 8192;
    constexpr int BSZ   = 16384;
    const int wr = (TM == 64) ? (wid & 1) : 0;
    const int wc = (TM == 64) ? (wid >> 1) : wid;

    float acc[2][4][4];
#pragma unroll
    for (int i = 0; i < 2; i++)
#pragma unroll
        for (int j = 0; j < 4; j++)
#pragma unroll
            for (int q = 0; q < 4; q++) acc[i][j][q] = 0.f;

    const int q = tid >> 3;
    uint32_t cbyte = (uint32_t)((tid & 7) << 4);
    const uint32_t swq = cbyte ^ (uint32_t)((q & 7) << 4);
    const uint32_t dq  = (uint32_t)q;
    const int ce = (tid & 7) << 3;
    const __nv_bfloat16* pah = Ah + (long)(m0 + q) * K + ce;
    const __nv_bfloat16* pal = Al + (long)(m0 + q) * K + ce;
    const __nv_bfloat16* pbh = Bh + (long)(n0 + q) * K + ce;
    const __nv_bfloat16* pbl = Bl + (long)(n0 + q) * K + ce;
    constexpr int RSTRIDE = (TM == 64) ? 32 : 16;
    constexpr int AU = 2;
    constexpr int BU = (TM == 64) ? 4 : 8;

#define LOAD_STAGE(sbuf, koff)                                                  \
    do {                                                                        \
        uint32_t base = sb + (sbuf) * (uint32_t)STAGE;                          \
        _Pragma("unroll")                                                       \
        for (int u = 0; u < AU; u++) {                                          \
            uint32_t row = dq + u * RSTRIDE;                                    \
            CP_ASYNC16(base + row * 128 + swq,                                  \
                       (const char*)(pah + (long)u * RSTRIDE * K + (koff)));    \
            CP_ASYNC16(base + AOFF + row * 128 + swq,                           \
                       (const char*)(pal + (long)u * RSTRIDE * K + (koff)));    \
        }                                                                       \
        _Pragma("unroll")                                                       \
        for (int u = 0; u < BU; u++) {                                          \
            uint32_t row = dq + u * RSTRIDE;                                    \
            CP_ASYNC16(base + BOFF + row * 128 + swq,                           \
                       (const char*)(pbh + (long)u * RSTRIDE * K + (koff)));    \
            CP_ASYNC16(base + BOFF + BSZ + row * 128 + swq,                     \
                       (const char*)(pbl + (long)u * RSTRIDE * K + (koff)));    \
        }                                                                       \
        CP_COMMIT();                                                            \
    } while (0)

    LOAD_STAGE(0, 0);

    for (int s = 0; s < NST; s++) {
        CP_WAIT0();
        __syncthreads();
        if (s + 1 < NST) LOAD_STAGE((s + 1) & 1, (s + 1) * 64);
        const uint32_t bufb = sb + (uint32_t)((s & 1) * STAGE);

#pragma unroll
        for (int ko = 0; ko < 64; ko += 16) {
            uint32_t afr[2][2][4];
            uint32_t bfr[2][2][4];
            {
                const int rowb = wr * 32 + (lane & 15);
                const int cb   = ko * 2 + ((lane >> 4) << 4);
#pragma unroll
                for (int t = 0; t < 2; t++)
#pragma unroll
                    for (int mi = 0; mi < 2; mi++) {
                        int row = rowb + mi * 16;
                        uint32_t addr = bufb + (uint32_t)(t * AOFF) + row * 128
                                      + (uint32_t)(cb ^ ((row & 7) << 4));
                        ldsm4(afr[t][mi], addr);
                    }
            }
            {
                const int rowb = wc * 32 + (lane & 7) + ((lane >> 4) << 3);
                const int cb   = ko * 2 + (((lane >> 3) & 1) << 4);
#pragma unroll
                for (int t = 0; t < 2; t++)
#pragma unroll
                    for (int nj = 0; nj < 2; nj++) {
                        int row = rowb + nj * 16;
                        uint32_t addr = bufb + (uint32_t)BOFF + (uint32_t)(t * BSZ)
                                      + row * 128 + (uint32_t)(cb ^ ((row & 7) << 4));
                        ldsm4(bfr[t][nj], addr);
                    }
            }
#pragma unroll
            for (int mi = 0; mi < 2; mi++)
#pragma unroll
                for (int nj = 0; nj < 2; nj++)
#pragma unroll
                    for (int hh = 0; hh < 2; hh++) {
                        const int nc = nj * 2 + hh;
                        const uint32_t bh0 = bfr[0][nj][hh * 2];
                        const uint32_t bh1 = bfr[0][nj][hh * 2 + 1];
                        const uint32_t bl0 = bfr[1][nj][hh * 2];
                        const uint32_t bl1 = bfr[1][nj][hh * 2 + 1];
                        mma16816(acc[mi][nc], afr[0][mi], bh0, bh1);
                        mma16816(acc[mi][nc], afr[0][mi], bl0, bl1);
                        mma16816(acc[mi][nc], afr[1][mi], bh0, bh1);
                    }
        }
        __syncthreads();
    }
#undef LOAD_STAGE

#pragma unroll
    for (int mi = 0; mi < 2; mi++)
#pragma unroll
        for (int nc = 0; nc < 4; nc++) {
            int row = m0 + wr * 32 + mi * 16 + (lane >> 2);
            int col = n0 + wc * 32 + nc * 8 + (lane & 3) * 2;
            float b0v = bias[col], b1v = bias[col + 1];
            float v0 = acc[mi][nc][0] + b0v;
            float v1 = acc[mi][nc][1] + b1v;
            float v2 = acc[mi][nc][2] + b0v;
            float v3 = acc[mi][nc][3] + b1v;
            if (RELU) {
                v0 = fmaxf(v0, 0.f); v1 = fmaxf(v1, 0.f);
                v2 = fmaxf(v2, 0.f); v3 = fmaxf(v3, 0.f);
            }
            if (WSPLIT) {
                __nv_bfloat16 h0, h1, h2, h3, l0, l1, l2, l3;
                split1(v0, h0, l0); split1(v1, h1, l1);
                split1(v2, h2, l2); split1(v3, h3, l3);
                *(__nv_bfloat162*)(Ch + (long)row * N + col)       = __nv_bfloat162(h0, h1);
                *(__nv_bfloat162*)(Ch + (long)(row + 8) * N + col) = __nv_bfloat162(h2, h3);
                *(__nv_bfloat162*)(Cl + (long)row * N + col)       = __nv_bfloat162(l0, l1);
                *(__nv_bfloat162*)(Cl + (long)(row + 8) * N + col) = __nv_bfloat162(l2, l3);
            } else {
                *(float2*)(C + (long)row * N + col)       = make_float2(v0, v1);
                *(float2*)(C + (long)(row + 8) * N + col) = make_float2(v2, v3);
            }
        }
}

__global__ __launch_bounds__(256) void gemm_qkv_tc(int l, const float* bias)
{ gemm_body<64, 768, 256, 0, 1>(g_acth, g_actl, g_wqkv_h + l*196608, g_wqkv_l + l*196608,
                                bias, nullptr, g_qkvh, g_qkvl); }
__global__ __launch_bounds__(128) void gemm_fc_tc(int l, const float* bias)
{ gemm_body<32, 256, 256, 0, 0>(g_acth, g_actl, g_wfc_h + l*65536, g_wfc_l + l*65536,
                                bias, g_tmp, nullptr, nullptr); }
__global__ __launch_bounds__(256) void gemm_w1_tc(int l, const float* bias)
{ gemm_body<64, 1024, 256, 1, 1>(g_acth, g_actl, g_w1_h + l*262144, g_w1_l + l*262144,
                                 bias, nullptr, g_hh, g_hl); }
__global__ __launch_bounds__(128) void gemm_w2_tc(int l, const float* bias)
{ gemm_body<32, 256, 1024, 0, 0>(g_hh, g_hl, g_w2_h + l*262144, g_w2_l + l*262144,
                                 bias, g_tmp, nullptr, nullptr); }
__global__ __launch_bounds__(256) void gemm_logits_tc(const float* bias, float* out)
{ gemm_body<64, 32000, 256, 0, 0>(g_acth, g_actl, g_wout_h, g_wout_l,
                                  bias, out, nullptr, nullptr); }

// ---------------------------------------------------------------------------
// Embedding + positional encoding
// ---------------------------------------------------------------------------
__global__ void embed_pos_kernel(const int* __restrict__ tok,
                                 const float* __restrict__ emb)
{
    int row = blockIdx.x;
    int d   = threadIdx.x;
    int t   = row & (Tn - 1);
    int token = tok[row];
    double div = exp(-(double)(d & ~1) * (9.210340371976184 / 256.0));
    double ang = (double)t * div;
    float  pe  = (d & 1) ? (float)cos(ang) : (float)sin(ang);
    float v = emb[token * Dn + d] + pe;
    g_x[row * Dn + d] = v;
    __nv_bfloat16 h, l;
    split1(v, h, l);
    g_acth[row * Dn + d] = h;
    g_actl[row * Dn + d] = l;
}

// ---------------------------------------------------------------------------
// HMMA flash attention, split-KV x8, FMA-poly softmax exp.
// ---------------------------------------------------------------------------
#define AQ_H  0
#define AQ_L  8192
#define AK_H  16384
#define AK_L  24576
#define AV_H  32768
#define AV_L  40960
#define AP_H  49152
#define AP_L  57344
#define ASMEM 65536
#define QSCALE 0.18033688f    /* 0.125 * log2(e) */

__global__ __launch_bounds__(128) void attn_kernel()
{
    extern __shared__ char smem[];
    const uint32_t sb = smem_to_u32(smem);
    const int tid  = threadIdx.x;
    const int lane = tid & 31;
    const int w    = tid >> 5;
    const int qt   = blockIdx.x;
    const int b    = blockIdx.y >> 2;
    const int h    = blockIdx.y & 3;
    const int half = blockIdx.z;
    const int q0   = qt << 6;
    const __nv_bfloat16* bh_ = g_qkvh + (long)b * Tn * 768 + h * 64;
    const __nv_bfloat16* bl_ = g_qkvl + (long)b * Tn * 768 + h * 64;

    const int lr  = tid & 63;
    const int cb0 = (tid >> 6) * 4;

    {
        const __nv_bfloat16* qh = bh_ + (long)(q0 + lr) * 768;
        const __nv_bfloat16* ql = bl_ + (long)(q0 + lr) * 768;
#pragma unroll
        for (int c = cb0; c < cb0 + 4; c++) {
            uint32_t off = (uint32_t)(lr * 128) + (uint32_t)((c * 16) ^ ((lr & 7) << 4));
            CP_ASYNC16(sb + AQ_H + off, qh + c * 8);
            CP_ASYNC16(sb + AQ_L + off, ql + c * 8);
        }
        CP_COMMIT();
    }

    float m_i[2] = {-1e30f, -1e30f};
    float l_i[2] = {0.f, 0.f};
    float oacc[8][4];
#pragma unroll
    for (int j = 0; j < 8; j++)
#pragma unroll
        for (int q = 0; q < 4; q++) oacc[j][q] = 0.f;

    const int nst = (qt >= half) ? ((qt - half) / NSPLIT + 1) : 0;

    for (int s = 0; s < nst; s++) {
        const int kt = half + NSPLIT * s;
        const int k0 = kt << 6;
        __syncthreads();
        {
            const __nv_bfloat16* kh = bh_ + (long)(k0 + lr) * 768 + 256;
            const __nv_bfloat16* kl = bl_ + (long)(k0 + lr) * 768 + 256;
            const __nv_bfloat16* vh = bh_ + (long)(k0 + lr) * 768 + 512;
            const __nv_bfloat16* vl = bl_ + (long)(k0 + lr) * 768 + 512;
#pragma unroll
            for (int c = cb0; c < cb0 + 4; c++) {
                uint32_t off = (uint32_t)(lr * 128)
                             + (uint32_t)((c * 16) ^ ((lr & 7) << 4));
                CP_ASYNC16(sb + AK_H + off, kh + c * 8);
                CP_ASYNC16(sb + AK_L + off, kl + c * 8);
                CP_ASYNC16(sb + AV_H + off, vh + c * 8);
                CP_ASYNC16(sb + AV_L + off, vl + c * 8);
            }
            CP_COMMIT();
        }
        CP_WAIT0();
        __syncthreads();

        float sacc[8][4];
#pragma unroll
        for (int j = 0; j < 8; j++)
#pragma unroll
            for (int q = 0; q < 4; q++) sacc[j][q] = 0.f;

#pragma unroll
        for (int ko4 = 0; ko4 < 4; ko4++) {
            uint32_t ah[4], al[4];
            {
                int arow = w * 16 + (lane & 15);
                uint32_t acb = (uint32_t)(ko4 * 32 + ((lane >> 4) << 4));
                uint32_t aoff = (uint32_t)(arow * 128) + (acb ^ ((uint32_t)(arow & 7) << 4));
                ldsm4(ah, sb + AQ_H + aoff);
                ldsm4(al, sb + AQ_L + aoff);
            }
#pragma unroll
            for (int nj = 0; nj < 4; nj++) {
                int brow = nj * 16 + (lane & 7) + ((lane >> 4) << 3);
                uint32_t bcb = (uint32_t)(ko4 * 32 + (((lane >> 3) & 1) << 4));
                uint32_t boff = (uint32_t)(brow * 128) + (bcb ^ ((uint32_t)(brow & 7) << 4));
                uint32_t bh[4], bl[4];
                ldsm4(bh, sb + AK_H + boff);
                ldsm4(bl, sb + AK_L + boff);
#pragma unroll
                for (int hh = 0; hh < 2; hh++) {
                    const int j = nj * 2 + hh;
                    mma16816(sacc[j], ah, bh[hh*2], bh[hh*2+1]);
                    mma16816(sacc[j], ah, bl[hh*2], bl[hh*2+1]);
                    mma16816(sacc[j], al, bh[hh*2], bh[hh*2+1]);
                }
            }
        }

#pragma unroll
        for (int j = 0; j < 8; j++)
#pragma unroll
            for (int q = 0; q < 4; q++) sacc[j][q] *= QSCALE;

        if (kt == qt) {
            const int r0 = lane >> 2;
            const int c0 = 2 * (lane & 3);
#pragma unroll
            for (int j = 0; j < 8; j++) {
                int c = j * 8 + c0;
                int rowA = w * 16 + r0;
                int rowB = rowA + 8;
                if (c     > rowA) sacc[j][0] = -1e30f;
                if (c + 1 > rowA) sacc[j][1] = -1e30f;
                if (c     > rowB) sacc[j][2] = -1e30f;
                if (c + 1 > rowB) sacc[j][3] = -1e30f;
            }
        }

#pragma unroll
        for (int rr = 0; rr < 2; rr++) {
            float mx = -1e30f;
#pragma unroll
            for (int j = 0; j < 8; j++)
                mx = fmaxf(mx, fmaxf(sacc[j][rr*2], sacc[j][rr*2+1]));
            mx = fmaxf(mx, __shfl_xor_sync(0xffffffffu, mx, 1));
            mx = fmaxf(mx, __shfl_xor_sync(0xffffffffu, mx, 2));
            float mn   = fmaxf(m_i[rr], mx);
            float corr = exp2_fma(m_i[rr] - mn);
            float rs = 0.f;
#pragma unroll
            for (int j = 0; j < 8; j++) {
                float p0 = exp2_fma(sacc[j][rr*2]   - mn);
                float p1 = exp2_fma(sacc[j][rr*2+1] - mn);
                sacc[j][rr*2] = p0; sacc[j][rr*2+1] = p1;
                rs += p0 + p1;
            }
            rs += __shfl_xor_sync(0xffffffffu, rs, 1);
            rs += __shfl_xor_sync(0xffffffffu, rs, 2);
            l_i[rr] = l_i[rr] * corr + rs;
            m_i[rr] = mn;
#pragma unroll
            for (int j = 0; j < 8; j++) {
                oacc[j][rr*2]   *= corr;
                oacc[j][rr*2+1] *= corr;
            }
        }

        {
            const int r0 = lane >> 2;
            const int c0 = 2 * (lane & 3);
#pragma unroll
            for (int rr = 0; rr < 2; rr++) {
                int row = w * 16 + r0 + rr * 8;
#pragma unroll
                for (int j = 0; j < 8; j++) {
                    int c = j * 8 + c0;
                    __nv_bfloat16 ph0, pl0, ph1, pl1;
                    split1(sacc[j][rr*2],   ph0, pl0);
                    split1(sacc[j][rr*2+1], ph1, pl1);
                    uint32_t off = (uint32_t)(row * 128)
                                 + (uint32_t)((c * 2) ^ ((row & 7) << 4));
                    __nv_bfloat162 th(ph0, ph1), tl(pl0, pl1);
                    *(uint32_t*)(smem + AP_H + off) = *(uint32_t*)&th;
                    *(uint32_t*)(smem + AP_L + off) = *(uint32_t*)&tl;
                }
            }
        }
        __syncwarp();

#pragma unroll
        for (int ko4 = 0; ko4 < 4; ko4++) {
            uint32_t ph[4], pl[4];
            {
                int arow = w * 16 + (lane & 15);
                uint32_t acb = (uint32_t)(ko4 * 32 + ((lane >> 4) << 4));
                uint32_t aoff = (uint32_t)(arow * 128) + (acb ^ ((uint32_t)(arow & 7) << 4));
                ldsm4(ph, sb + AP_H + aoff);
                ldsm4(pl, sb + AP_L + aoff);
            }
#pragma unroll
            for (int nj = 0; nj < 4; nj++) {
                int brow = ko4 * 16 + (lane & 7) + (((lane >> 3) & 1) << 3);
                uint32_t bcb = (uint32_t)(nj * 32 + ((lane >> 4) << 4));
                uint32_t boff = (uint32_t)(brow * 128) + (bcb ^ ((uint32_t)(brow & 7) << 4));
                uint32_t vh[4], vl[4];
                ldsm4t(vh, sb + AV_H + boff);
                ldsm4t(vl, sb + AV_L + boff);
#pragma unroll
                for (int hh = 0; hh < 2; hh++) {
                    const int j = nj * 2 + hh;
                    mma16816(oacc[j], ph, vh[hh*2], vh[hh*2+1]);
                    mma16816(oacc[j], ph, vl[hh*2], vl[hh*2+1]);
                    mma16816(oacc[j], pl, vh[hh*2], vh[hh*2+1]);
                }
            }
        }
    }

    float* attp = g_attp[half];
#pragma unroll
    for (int rr = 0; rr < 2; rr++) {
        int row  = w * 16 + (lane >> 2) + rr * 8;
        int grow = b * Tn + q0 + row;
        long gbase = (long)grow * Dn + h * 64;
#pragma unroll
        for (int j = 0; j < 8; j++) {
            int c = j * 8 + 2 * (lane & 3);
            *(float2*)(attp + gbase + c) = make_float2(oacc[j][rr*2], oacc[j][rr*2+1]);
        }
        if ((lane & 3) == 0) {
            g_pm[half][grow * 4 + h] = m_i[rr];
            g_pl[half][grow * 4 + h] = l_i[rr];
        }
    }
}

// ---------------------------------------------------------------------------
// Combine split-KV partials -> bf16 hi/lo activations.
// ---------------------------------------------------------------------------
__global__ void attn_combine()
{
    int idx = blockIdx.x * 256 + threadIdx.x;
    int row = idx >> 6;
    int dq  = (idx & 63) << 2;
    int h   = dq >> 6;
    float m = -1e30f;
#pragma unroll
    for (int p = 0; p < NSPLIT; p++) m = fmaxf(m, g_pm[p][row * 4 + h]);
    float c[NSPLIT], lsum = 0.f;
#pragma unroll
    for (int p = 0; p < NSPLIT; p++) {
        c[p] = ex2f(g_pm[p][row * 4 + h] - m);
        lsum = fmaf(g_pl[p][row * 4 + h], c[p], lsum);
    }
    float inv = 1.f / lsum;
    long base = (long)row * Dn + dq;
    float v0 = 0.f, v1 = 0.f, v2 = 0.f, v3 = 0.f;
#pragma unroll
    for (int p = 0; p < NSPLIT; p++) {
        float4 pv = *(float4*)(g_attp[p] + base);
        v0 = fmaf(pv.x, c[p], v0);
        v1 = fmaf(pv.y, c[p], v1);
        v2 = fmaf(pv.z, c[p], v2);
        v3 = fmaf(pv.w, c[p], v3);
    }
    v0 *= inv; v1 *= inv; v2 *= inv; v3 *= inv;
    __nv_bfloat16 h0,h1,h2,h3,l0b,l1b,l2b,l3b;
    split1(v0,h0,l0b); split1(v1,h1,l1b); split1(v2,h2,l2b); split1(v3,h3,l3b);
    *(__nv_bfloat162*)(g_acth + base)     = __nv_bfloat162(h0, h1);
    *(__nv_bfloat162*)(g_acth + base + 2) = __nv_bfloat162(h2, h3);
    *(__nv_bfloat162*)(g_actl + base)     = __nv_bfloat162(l0b, l1b);
    *(__nv_bfloat162*)(g_actl + base + 2) = __nv_bfloat162(l2b, l3b);
}

// ---------------------------------------------------------------------------
// LayerNorm: x = LN(x [+ g_tmp]) * sc + bi ; writes x fp32 AND hi/lo bf16.
// ---------------------------------------------------------------------------
template<int ADD>
__device__ __forceinline__ void ln_body(const float* __restrict__ sc,
                                        const float* __restrict__ bi)
{
    int row  = blockIdx.x * 8 + (threadIdx.x >> 5);
    int lane = threadIdx.x & 31;
    const float* pa = g_x + (long)row * Dn + lane * 8;
    float v[8];
    {
        float4 v0 = *(const float4*)pa;
        float4 v1 = *(const float4*)(pa + 4);
        v[0] = v0.x; v[1] = v0.y; v[2] = v0.z; v[3] = v0.w;
        v[4] = v1.x; v[5] = v1.y; v[6] = v1.z; v[7] = v1.w;
    }
    if (ADD) {
        const float* pr = g_tmp + (long)row * Dn + lane * 8;
        float4 r0 = *(const float4*)pr;
        float4 r1 = *(const float4*)(pr + 4);
        v[0] += r0.x; v[1] += r0.y; v[2] += r0.z; v[3] += r0.w;
        v[4] += r1.x; v[5] += r1.y; v[6] += r1.z; v[7] += r1.w;
    }
    float s = 0.f;
#pragma unroll
    for (int k = 0; k < 8; k++) s += v[k];
#pragma unroll
    for (int ofs = 16; ofs; ofs >>= 1) s += __shfl_xor_sync(0xffffffffu, s, ofs);
    float mu = s * (1.f / 256.f);
    float var = 0.f;
#pragma unroll
    for (int k = 0; k < 8; k++) { float d = v[k] - mu; var = fmaf(d, d, var); }
#pragma unroll
    for (int ofs = 16; ofs; ofs >>= 1) var += __shfl_xor_sync(0xffffffffu, var, ofs);
    float rstd = rsqrtf(var * (1.f / 256.f) + 1e-5f);

    float4 s0 = *(const float4*)(sc + lane * 8);
    float4 s1 = *(const float4*)(sc + lane * 8 + 4);
    float4 b0 = *(const float4*)(bi + lane * 8);
    float4 b1 = *(const float4*)(bi + lane * 8 + 4);
    float scv[8] = {s0.x, s0.y, s0.z, s0.w, s1.x, s1.y, s1.z, s1.w};
    float biv[8] = {b0.x, b0.y, b0.z, b0.w, b1.x, b1.y, b1.z, b1.w};
    float o[8];
    __nv_bfloat16 oh[8], ol[8];
#pragma unroll
    for (int k = 0; k < 8; k++) {
        o[k] = fmaf((v[k] - mu) * rstd, scv[k], biv[k]);
        split1(o[k], oh[k], ol[k]);
    }
    long base = (long)row * Dn + lane * 8;
    *(float4*)(g_x + base)     = make_float4(o[0], o[1], o[2], o[3]);
    *(float4*)(g_x + base + 4) = make_float4(o[4], o[5], o[6], o[7]);
#pragma unroll
    for (int k = 0; k < 4; k++) {
        ((__nv_bfloat162*)(g_acth + base))[k] = __nv_bfloat162(oh[2*k], oh[2*k+1]);
        ((__nv_bfloat162*)(g_actl + base))[k] = __nv_bfloat162(ol[2*k], ol[2*k+1]);
    }
}
__global__ void add_ln_kernel(const float* sc, const float* bi) { ln_body<1>(sc, bi); }
__global__ void final_ln_kernel(const float* sc, const float* bi) { ln_body<0>(sc, bi); }

// ---------------------------------------------------------------------------
// Orchestration
// ---------------------------------------------------------------------------
extern "C" void kernel_launch(void* const* d_in, const int* in_sizes, int n_in,
                              void* d_out, int out_size)
{
    const int*   tokens = (const int*)d_in[0];
    const float* embedw = (const float*)d_in[1];
    const float* qkv_w  = (const float*)d_in[2];
    const float* qkv_b  = (const float*)d_in[3];
    const float* fc_w   = (const float*)d_in[4];
    const float* fc_b   = (const float*)d_in[5];
    const float* ln1_s  = (const float*)d_in[6];
    const float* ln1_b  = (const float*)d_in[7];
    const float* w1     = (const float*)d_in[8];
    const float* b1     = (const float*)d_in[9];
    const float* w2     = (const float*)d_in[10];
    const float* b2     = (const float*)d_in[11];
    const float* ln2_s  = (const float*)d_in[12];
    const float* ln2_b  = (const float*)d_in[13];
    const float* lnf_s  = (const float*)d_in[14];
    const float* lnf_b  = (const float*)d_in[15];
    const float* out_w  = (const float*)d_in[16];
    const float* out_b  = (const float*)d_in[17];
    float* logits = (float*)d_out;

    cudaFuncSetAttribute((const void*)gemm_qkv_tc,
        cudaFuncAttributeMaxDynamicSharedMemorySize, GSMEM64);
    cudaFuncSetAttribute((const void*)gemm_fc_tc,
        cudaFuncAttributeMaxDynamicSharedMemorySize, GSMEM32);
    cudaFuncSetAttribute((const void*)gemm_w1_tc,
        cudaFuncAttributeMaxDynamicSharedMemorySize, GSMEM64);
    cudaFuncSetAttribute((const void*)gemm_w2_tc,
        cudaFuncAttributeMaxDynamicSharedMemorySize, GSMEM32);
    cudaFuncSetAttribute((const void*)gemm_logits_tc,
        cudaFuncAttributeMaxDynamicSharedMemorySize, GSMEM64);
    cudaFuncSetAttribute((const void*)attn_kernel,
        cudaFuncAttributeMaxDynamicSharedMemorySize, ASMEM);

    split_weights<<<2048, 256>>>(qkv_w, fc_w, w1, w2, out_w);
    embed_pos_kernel<<<Mrows, Dn>>>(tokens, embedw);

    for (int l = 0; l < 4; l++) {
        gemm_qkv_tc<<<dim3(6, 64), 256, GSMEM64>>>(l, qkv_b + l * 768);
        attn_kernel<<<dim3(32, Bn * 4, NSPLIT), 128, ASMEM>>>();
        attn_combine<<<1024, 256>>>();
        gemm_fc_tc<<<dim3(2, 128), 128, GSMEM32>>>(l, fc_b + l * 256);
        add_ln_kernel<<<Mrows / 8, 256>>>(ln1_s + l * 256, ln1_b + l * 256);
        gemm_w1_tc<<<dim3(8, 64), 256, GSMEM64>>>(l, b1 + l * 1024);
        gemm_w2_tc<<<dim3(2, 128), 128, GSMEM32>>>(l, b2 + l * 256);
        add_ln_kernel<<<Mrows / 8, 256>>>(ln2_s + l * 256, ln2_b + l * 256);
    }
    final_ln_kernel<<<Mrows / 8, 256>>>(lnf_s, lnf_b);
    gemm_logits_tc<<<dim3(250, 64), 256, GSMEM64>>>(out_b, logits);
}

// round 14
// speedup vs baseline: 1.0180x; 1.0180x over previous
#include <cuda_runtime.h>
#include <cuda_bf16.h>
#include <math.h>
#include <stdint.h>

// ---------------------------------------------------------------------------
// MiniGPT forward. B=2 T=2048 D=256 H=4 DK=64 DFF=1024 L=4 V=32000
// GEMMs: mma.sync bf16x3. qkv/w1/logits TM=64, fc/w2 TM=32.
// Attention: HMMA flash, split-KV x8, MUFU ex2 softmax (poly-exp falsified
// twice), empty-split early exit + bounded combine.
// ---------------------------------------------------------------------------

#define Tn    2048
#define Bn    2
#define Dn    256
#define Mrows 4096
#define NSPLIT 8

// fp32 scratch
__device__ float g_x[Mrows * Dn];
__device__ float g_tmp[Mrows * Dn];

// attention split-KV partials
__device__ float g_attp[NSPLIT][Mrows * Dn];
__device__ float g_pm[NSPLIT][Mrows * 4];
__device__ float g_pl[NSPLIT][Mrows * 4];

// bf16 hi/lo activations, qkv, MLP hidden
__device__ __nv_bfloat16 g_acth[Mrows * Dn],  g_actl[Mrows * Dn];
__device__ __nv_bfloat16 g_qkvh[Mrows * 768], g_qkvl[Mrows * 768];
__device__ __nv_bfloat16 g_hh[Mrows * 1024],  g_hl[Mrows * 1024];

// bf16 hi/lo weights
__device__ __nv_bfloat16 g_wqkv_h[4 * 768 * 256],  g_wqkv_l[4 * 768 * 256];
__device__ __nv_bfloat16 g_wfc_h [4 * 256 * 256],  g_wfc_l [4 * 256 * 256];
__device__ __nv_bfloat16 g_w1_h  [4 * 1024 * 256], g_w1_l  [4 * 1024 * 256];
__device__ __nv_bfloat16 g_w2_h  [4 * 256 * 1024], g_w2_l  [4 * 256 * 1024];
__device__ __nv_bfloat16 g_wout_h[32000 * 256],    g_wout_l[32000 * 256];

// ---------------------------------------------------------------------------
// PTX helpers
// ---------------------------------------------------------------------------
__device__ __forceinline__ uint32_t smem_to_u32(const void* p) {
    uint32_t a;
    asm("{ .reg .u64 t; cvta.to.shared.u64 t, %1; cvt.u32.u64 %0, t; }"
        : "=r"(a) : "l"(p));
    return a;
}
__device__ __forceinline__ void ldsm4(uint32_t* r, uint32_t addr) {
    asm volatile("ldmatrix.sync.aligned.m8n8.x4.shared.b16 {%0,%1,%2,%3}, [%4];"
                 : "=r"(r[0]), "=r"(r[1]), "=r"(r[2]), "=r"(r[3]) : "r"(addr));
}
__device__ __forceinline__ void ldsm4t(uint32_t* r, uint32_t addr) {
    asm volatile("ldmatrix.sync.aligned.m8n8.x4.trans.shared.b16 {%0,%1,%2,%3}, [%4];"
                 : "=r"(r[0]), "=r"(r[1]), "=r"(r[2]), "=r"(r[3]) : "r"(addr));
}
__device__ __forceinline__ void mma16816(float* d, const uint32_t* a,
                                         uint32_t b0, uint32_t b1) {
    asm volatile(
        "mma.sync.aligned.m16n8k16.row.col.f32.bf16.bf16.f32 "
        "{%0,%1,%2,%3}, {%4,%5,%6,%7}, {%8,%9}, {%0,%1,%2,%3};"
        : "+f"(d[0]), "+f"(d[1]), "+f"(d[2]), "+f"(d[3])
        : "r"(a[0]), "r"(a[1]), "r"(a[2]), "r"(a[3]), "r"(b0), "r"(b1));
}
__device__ __forceinline__ float ex2f(float x) {
    float y;
    asm("ex2.approx.f32 %0, %1;" : "=f"(y) : "f"(x));
    return y;
}
#define CP_ASYNC16(dst, src) \
    asm volatile("cp.async.cg.shared.global [%0], [%1], 16;" \
                 :: "r"(dst), "l"(src) : "memory")
#define CP_COMMIT()  asm volatile("cp.async.commit_group;" ::: "memory")
#define CP_WAIT0()   asm volatile("cp.async.wait_group 0;" ::: "memory")

__device__ __forceinline__ void split1(float v, __nv_bfloat16& h, __nv_bfloat16& l) {
    h = __float2bfloat16(v);
    l = __float2bfloat16(v - __bfloat162float(h));
}

// ---------------------------------------------------------------------------
// Fused weight split
// ---------------------------------------------------------------------------
__global__ void split_weights(const float* __restrict__ qkv_w,
                              const float* __restrict__ fc_w,
                              const float* __restrict__ w1,
                              const float* __restrict__ w2,
                              const float* __restrict__ out_w)
{
    const int c0 = 196608, c1 = c0 + 65536, c2 = c1 + 262144,
              c3 = c2 + 262144, c4 = c3 + 2048000;
    int stride = gridDim.x * blockDim.x;
    for (int idx = blockIdx.x * blockDim.x + threadIdx.x; idx < c4; idx += stride) {
        const float* src; __nv_bfloat16 *dh, *dl; int li;
        if (idx < c0)      { src = qkv_w; dh = g_wqkv_h; dl = g_wqkv_l; li = idx; }
        else if (idx < c1) { src = fc_w;  dh = g_wfc_h;  dl = g_wfc_l;  li = idx - c0; }
        else if (idx < c2) { src = w1;    dh = g_w1_h;   dl = g_w1_l;   li = idx - c1; }
        else if (idx < c3) { src = w2;    dh = g_w2_h;   dl = g_w2_l;   li = idx - c2; }
        else               { src = out_w; dh = g_wout_h; dl = g_wout_l; li = idx - c3; }
        float4 v = ((const float4*)src)[li];
        __nv_bfloat16 h0, h1, h2, h3, l0, l1, l2, l3;
        split1(v.x, h0, l0); split1(v.y, h1, l1);
        split1(v.z, h2, l2); split1(v.w, h3, l3);
        ((__nv_bfloat162*)dh)[li * 2 + 0] = __nv_bfloat162(h0, h1);
        ((__nv_bfloat162*)dh)[li * 2 + 1] = __nv_bfloat162(h2, h3);
        ((__nv_bfloat162*)dl)[li * 2 + 0] = __nv_bfloat162(l0, l1);
        ((__nv_bfloat162*)dl)[li * 2 + 1] = __nv_bfloat162(l2, l3);
    }
}

// ---------------------------------------------------------------------------
// mma.sync bf16x3 GEMM. TM in {64, 32}, TN = 128. (unchanged from R12)
// ---------------------------------------------------------------------------
#define GSMEM64  (2 * 49152)
#define GSMEM32  (2 * 40960)

template<int TM, int N, int K, int RELU, int WSPLIT>
__device__ __forceinline__ void gemm_body(
    const __nv_bfloat16* __restrict__ Ah, const __nv_bfloat16* __restrict__ Al,
    const __nv_bfloat16* __restrict__ Bh, const __nv_bfloat16* __restrict__ Bl,
    const float* __restrict__ bias, float* __restrict__ C,
    __nv_bfloat16* __restrict__ Ch, __nv_bfloat16* __restrict__ Cl)
{
    extern __shared__ char smem[];
    const uint32_t sb = smem_to_u32(smem);
    const int tid  = threadIdx.x;
    const int wid  = tid >> 5;
    const int lane = tid & 31;
    const int m0   = blockIdx.y * TM;
    const int n0   = blockIdx.x << 7;
    constexpr int NST   = K / 64;
    constexpr int STAGE = (TM == 64) ? 49152 : 40960;
    constexpr int AOFF  = (TM == 64) ? 8192 : 4096;
    constexpr int BOFF  = (TM == 64) ? 16384 : 8192;
    constexpr int BSZ   = 16384;
    const int wr = (TM == 64) ? (wid & 1) : 0;
    const int wc = (TM == 64) ? (wid >> 1) : wid;

    float acc[2][4][4];
#pragma unroll
    for (int i = 0; i < 2; i++)
#pragma unroll
        for (int j = 0; j < 4; j++)
#pragma unroll
            for (int q = 0; q < 4; q++) acc[i][j][q] = 0.f;

    const int q = tid >> 3;
    uint32_t cbyte = (uint32_t)((tid & 7) << 4);
    const uint32_t swq = cbyte ^ (uint32_t)((q & 7) << 4);
    const uint32_t dq  = (uint32_t)q;
    const int ce = (tid & 7) << 3;
    const __nv_bfloat16* pah = Ah + (long)(m0 + q) * K + ce;
    const __nv_bfloat16* pal = Al + (long)(m0 + q) * K + ce;
    const __nv_bfloat16* pbh = Bh + (long)(n0 + q) * K + ce;
    const __nv_bfloat16* pbl = Bl + (long)(n0 + q) * K + ce;
    constexpr int RSTRIDE = (TM == 64) ? 32 : 16;
    constexpr int AU = 2;
    constexpr int BU = (TM == 64) ? 4 : 8;

#define LOAD_STAGE(sbuf, koff)                                                  \
    do {                                                                        \
        uint32_t base = sb + (sbuf) * (uint32_t)STAGE;                          \
        _Pragma("unroll")                                                       \
        for (int u = 0; u < AU; u++) {                                          \
            uint32_t row = dq + u * RSTRIDE;                                    \
            CP_ASYNC16(base + row * 128 + swq,                                  \
                       (const char*)(pah + (long)u * RSTRIDE * K + (koff)));    \
            CP_ASYNC16(base + AOFF + row * 128 + swq,                           \
                       (const char*)(pal + (long)u * RSTRIDE * K + (koff)));    \
        }                                                                       \
        _Pragma("unroll")                                                       \
        for (int u = 0; u < BU; u++) {                                          \
            uint32_t row = dq + u * RSTRIDE;                                    \
            CP_ASYNC16(base + BOFF + row * 128 + swq,                           \
                       (const char*)(pbh + (long)u * RSTRIDE * K + (koff)));    \
            CP_ASYNC16(base + BOFF + BSZ + row * 128 + swq,                     \
                       (const char*)(pbl + (long)u * RSTRIDE * K + (koff)));    \
        }                                                                       \
        CP_COMMIT();                                                            \
    } while (0)

    LOAD_STAGE(0, 0);

    for (int s = 0; s < NST; s++) {
        CP_WAIT0();
        __syncthreads();
        if (s + 1 < NST) LOAD_STAGE((s + 1) & 1, (s + 1) * 64);
        const uint32_t bufb = sb + (uint32_t)((s & 1) * STAGE);

#pragma unroll
        for (int ko = 0; ko < 64; ko += 16) {
            uint32_t afr[2][2][4];
            uint32_t bfr[2][2][4];
            {
                const int rowb = wr * 32 + (lane & 15);
                const int cb   = ko * 2 + ((lane >> 4) << 4);
#pragma unroll
                for (int t = 0; t < 2; t++)
#pragma unroll
                    for (int mi = 0; mi < 2; mi++) {
                        int row = rowb + mi * 16;
                        uint32_t addr = bufb + (uint32_t)(t * AOFF) + row * 128
                                      + (uint32_t)(cb ^ ((row & 7) << 4));
                        ldsm4(afr[t][mi], addr);
                    }
            }
            {
                const int rowb = wc * 32 + (lane & 7) + ((lane >> 4) << 3);
                const int cb   = ko * 2 + (((lane >> 3) & 1) << 4);
#pragma unroll
                for (int t = 0; t < 2; t++)
#pragma unroll
                    for (int nj = 0; nj < 2; nj++) {
                        int row = rowb + nj * 16;
                        uint32_t addr = bufb + (uint32_t)BOFF + (uint32_t)(t * BSZ)
                                      + row * 128 + (uint32_t)(cb ^ ((row & 7) << 4));
                        ldsm4(bfr[t][nj], addr);
                    }
            }
#pragma unroll
            for (int mi = 0; mi < 2; mi++)
#pragma unroll
                for (int nj = 0; nj < 2; nj++)
#pragma unroll
                    for (int hh = 0; hh < 2; hh++) {
                        const int nc = nj * 2 + hh;
                        const uint32_t bh0 = bfr[0][nj][hh * 2];
                        const uint32_t bh1 = bfr[0][nj][hh * 2 + 1];
                        const uint32_t bl0 = bfr[1][nj][hh * 2];
                        const uint32_t bl1 = bfr[1][nj][hh * 2 + 1];
                        mma16816(acc[mi][nc], afr[0][mi], bh0, bh1);
                        mma16816(acc[mi][nc], afr[0][mi], bl0, bl1);
                        mma16816(acc[mi][nc], afr[1][mi], bh0, bh1);
                    }
        }
        __syncthreads();
    }
#undef LOAD_STAGE

#pragma unroll
    for (int mi = 0; mi < 2; mi++)
#pragma unroll
        for (int nc = 0; nc < 4; nc++) {
            int row = m0 + wr * 32 + mi * 16 + (lane >> 2);
            int col = n0 + wc * 32 + nc * 8 + (lane & 3) * 2;
            float b0v = bias[col], b1v = bias[col + 1];
            float v0 = acc[mi][nc][0] + b0v;
            float v1 = acc[mi][nc][1] + b1v;
            float v2 = acc[mi][nc][2] + b0v;
            float v3 = acc[mi][nc][3] + b1v;
            if (RELU) {
                v0 = fmaxf(v0, 0.f); v1 = fmaxf(v1, 0.f);
                v2 = fmaxf(v2, 0.f); v3 = fmaxf(v3, 0.f);
            }
            if (WSPLIT) {
                __nv_bfloat16 h0, h1, h2, h3, l0, l1, l2, l3;
                split1(v0, h0, l0); split1(v1, h1, l1);
                split1(v2, h2, l2); split1(v3, h3, l3);
                *(__nv_bfloat162*)(Ch + (long)row * N + col)       = __nv_bfloat162(h0, h1);
                *(__nv_bfloat162*)(Ch + (long)(row + 8) * N + col) = __nv_bfloat162(h2, h3);
                *(__nv_bfloat162*)(Cl + (long)row * N + col)       = __nv_bfloat162(l0, l1);
                *(__nv_bfloat162*)(Cl + (long)(row + 8) * N + col) = __nv_bfloat162(l2, l3);
            } else {
                *(float2*)(C + (long)row * N + col)       = make_float2(v0, v1);
                *(float2*)(C + (long)(row + 8) * N + col) = make_float2(v2, v3);
            }
        }
}

__global__ __launch_bounds__(256) void gemm_qkv_tc(int l, const float* bias)
{ gemm_body<64, 768, 256, 0, 1>(g_acth, g_actl, g_wqkv_h + l*196608, g_wqkv_l + l*196608,
                                bias, nullptr, g_qkvh, g_qkvl); }
__global__ __launch_bounds__(128) void gemm_fc_tc(int l, const float* bias)
{ gemm_body<32, 256, 256, 0, 0>(g_acth, g_actl, g_wfc_h + l*65536, g_wfc_l + l*65536,
                                bias, g_tmp, nullptr, nullptr); }
__global__ __launch_bounds__(256) void gemm_w1_tc(int l, const float* bias)
{ gemm_body<64, 1024, 256, 1, 1>(g_acth, g_actl, g_w1_h + l*262144, g_w1_l + l*262144,
                                 bias, nullptr, g_hh, g_hl); }
__global__ __launch_bounds__(128) void gemm_w2_tc(int l, const float* bias)
{ gemm_body<32, 256, 1024, 0, 0>(g_hh, g_hl, g_w2_h + l*262144, g_w2_l + l*262144,
                                 bias, g_tmp, nullptr, nullptr); }
__global__ __launch_bounds__(256) void gemm_logits_tc(const float* bias, float* out)
{ gemm_body<64, 32000, 256, 0, 0>(g_acth, g_actl, g_wout_h, g_wout_l,
                                  bias, out, nullptr, nullptr); }

// ---------------------------------------------------------------------------
// Embedding + positional encoding
// ---------------------------------------------------------------------------
__global__ void embed_pos_kernel(const int* __restrict__ tok,
                                 const float* __restrict__ emb)
{
    int row = blockIdx.x;
    int d   = threadIdx.x;
    int t   = row & (Tn - 1);
    int token = tok[row];
    double div = exp(-(double)(d & ~1) * (9.210340371976184 / 256.0));
    double ang = (double)t * div;
    float  pe  = (d & 1) ? (float)cos(ang) : (float)sin(ang);
    float v = emb[token * Dn + d] + pe;
    g_x[row * Dn + d] = v;
    __nv_bfloat16 h, l;
    split1(v, h, l);
    g_acth[row * Dn + d] = h;
    g_actl[row * Dn + d] = l;
}

// ---------------------------------------------------------------------------
// HMMA flash attention, split-KV x8, MUFU ex2 softmax. Blocks with no
// assigned KV tiles exit before the prologue (combine never reads them).
// ---------------------------------------------------------------------------
#define AQ_H  0
#define AQ_L  8192
#define AK_H  16384
#define AK_L  24576
#define AV_H  32768
#define AV_L  40960
#define AP_H  49152
#define AP_L  57344
#define ASMEM 65536
#define QSCALE 0.18033688f    /* 0.125 * log2(e) */

__global__ __launch_bounds__(128) void attn_kernel()
{
    extern __shared__ char smem[];
    const uint32_t sb = smem_to_u32(smem);
    const int tid  = threadIdx.x;
    const int lane = tid & 31;
    const int w    = tid >> 5;
    const int qt   = blockIdx.x;
    const int b    = blockIdx.y >> 2;
    const int h    = blockIdx.y & 3;
    const int half = blockIdx.z;
    const int q0   = qt << 6;

    const int nst = (qt >= half) ? ((qt - half) / NSPLIT + 1) : 0;
    if (nst == 0) return;          // uniform per-block; no syncs issued yet

    const __nv_bfloat16* bh_ = g_qkvh + (long)b * Tn * 768 + h * 64;
    const __nv_bfloat16* bl_ = g_qkvl + (long)b * Tn * 768 + h * 64;

    const int lr  = tid & 63;
    const int cb0 = (tid >> 6) * 4;

    {
        const __nv_bfloat16* qh = bh_ + (long)(q0 + lr) * 768;
        const __nv_bfloat16* ql = bl_ + (long)(q0 + lr) * 768;
#pragma unroll
        for (int c = cb0; c < cb0 + 4; c++) {
            uint32_t off = (uint32_t)(lr * 128) + (uint32_t)((c * 16) ^ ((lr & 7) << 4));
            CP_ASYNC16(sb + AQ_H + off, qh + c * 8);
            CP_ASYNC16(sb + AQ_L + off, ql + c * 8);
        }
        CP_COMMIT();
    }

    float m_i[2] = {-1e30f, -1e30f};
    float l_i[2] = {0.f, 0.f};
    float oacc[8][4];
#pragma unroll
    for (int j = 0; j < 8; j++)
#pragma unroll
        for (int q = 0; q < 4; q++) oacc[j][q] = 0.f;

    for (int s = 0; s < nst; s++) {
        const int kt = half + NSPLIT * s;
        const int k0 = kt << 6;
        __syncthreads();
        {
            const __nv_bfloat16* kh = bh_ + (long)(k0 + lr) * 768 + 256;
            const __nv_bfloat16* kl = bl_ + (long)(k0 + lr) * 768 + 256;
            const __nv_bfloat16* vh = bh_ + (long)(k0 + lr) * 768 + 512;
            const __nv_bfloat16* vl = bl_ + (long)(k0 + lr) * 768 + 512;
#pragma unroll
            for (int c = cb0; c < cb0 + 4; c++) {
                uint32_t off = (uint32_t)(lr * 128)
                             + (uint32_t)((c * 16) ^ ((lr & 7) << 4));
                CP_ASYNC16(sb + AK_H + off, kh + c * 8);
                CP_ASYNC16(sb + AK_L + off, kl + c * 8);
                CP_ASYNC16(sb + AV_H + off, vh + c * 8);
                CP_ASYNC16(sb + AV_L + off, vl + c * 8);
            }
            CP_COMMIT();
        }
        CP_WAIT0();
        __syncthreads();

        float sacc[8][4];
#pragma unroll
        for (int j = 0; j < 8; j++)
#pragma unroll
            for (int q = 0; q < 4; q++) sacc[j][q] = 0.f;

#pragma unroll
        for (int ko4 = 0; ko4 < 4; ko4++) {
            uint32_t ah[4], al[4];
            {
                int arow = w * 16 + (lane & 15);
                uint32_t acb = (uint32_t)(ko4 * 32 + ((lane >> 4) << 4));
                uint32_t aoff = (uint32_t)(arow * 128) + (acb ^ ((uint32_t)(arow & 7) << 4));
                ldsm4(ah, sb + AQ_H + aoff);
                ldsm4(al, sb + AQ_L + aoff);
            }
#pragma unroll
            for (int nj = 0; nj < 4; nj++) {
                int brow = nj * 16 + (lane & 7) + ((lane >> 4) << 3);
                uint32_t bcb = (uint32_t)(ko4 * 32 + (((lane >> 3) & 1) << 4));
                uint32_t boff = (uint32_t)(brow * 128) + (bcb ^ ((uint32_t)(brow & 7) << 4));
                uint32_t bh[4], bl[4];
                ldsm4(bh, sb + AK_H + boff);
                ldsm4(bl, sb + AK_L + boff);
#pragma unroll
                for (int hh = 0; hh < 2; hh++) {
                    const int j = nj * 2 + hh;
                    mma16816(sacc[j], ah, bh[hh*2], bh[hh*2+1]);
                    mma16816(sacc[j], ah, bl[hh*2], bl[hh*2+1]);
                    mma16816(sacc[j], al, bh[hh*2], bh[hh*2+1]);
                }
            }
        }

#pragma unroll
        for (int j = 0; j < 8; j++)
#pragma unroll
            for (int q = 0; q < 4; q++) sacc[j][q] *= QSCALE;

        if (kt == qt) {
            const int r0 = lane >> 2;
            const int c0 = 2 * (lane & 3);
#pragma unroll
            for (int j = 0; j < 8; j++) {
                int c = j * 8 + c0;
                int rowA = w * 16 + r0;
                int rowB = rowA + 8;
                if (c     > rowA) sacc[j][0] = -1e30f;
                if (c + 1 > rowA) sacc[j][1] = -1e30f;
                if (c     > rowB) sacc[j][2] = -1e30f;
                if (c + 1 > rowB) sacc[j][3] = -1e30f;
            }
        }

#pragma unroll
        for (int rr = 0; rr < 2; rr++) {
            float mx = -1e30f;
#pragma unroll
            for (int j = 0; j < 8; j++)
                mx = fmaxf(mx, fmaxf(sacc[j][rr*2], sacc[j][rr*2+1]));
            mx = fmaxf(mx, __shfl_xor_sync(0xffffffffu, mx, 1));
            mx = fmaxf(mx, __shfl_xor_sync(0xffffffffu, mx, 2));
            float mn   = fmaxf(m_i[rr], mx);
            float corr = ex2f(m_i[rr] - mn);
            float rs = 0.f;
#pragma unroll
            for (int j = 0; j < 8; j++) {
                float p0 = ex2f(sacc[j][rr*2]   - mn);
                float p1 = ex2f(sacc[j][rr*2+1] - mn);
                sacc[j][rr*2] = p0; sacc[j][rr*2+1] = p1;
                rs += p0 + p1;
            }
            rs += __shfl_xor_sync(0xffffffffu, rs, 1);
            rs += __shfl_xor_sync(0xffffffffu, rs, 2);
            l_i[rr] = l_i[rr] * corr + rs;
            m_i[rr] = mn;
#pragma unroll
            for (int j = 0; j < 8; j++) {
                oacc[j][rr*2]   *= corr;
                oacc[j][rr*2+1] *= corr;
            }
        }

        {
            const int r0 = lane >> 2;
            const int c0 = 2 * (lane & 3);
#pragma unroll
            for (int rr = 0; rr < 2; rr++) {
                int row = w * 16 + r0 + rr * 8;
#pragma unroll
                for (int j = 0; j < 8; j++) {
                    int c = j * 8 + c0;
                    __nv_bfloat16 ph0, pl0, ph1, pl1;
                    split1(sacc[j][rr*2],   ph0, pl0);
                    split1(sacc[j][rr*2+1], ph1, pl1);
                    uint32_t off = (uint32_t)(row * 128)
                                 + (uint32_t)((c * 2) ^ ((row & 7) << 4));
                    __nv_bfloat162 th(ph0, ph1), tl(pl0, pl1);
                    *(uint32_t*)(smem + AP_H + off) = *(uint32_t*)&th;
                    *(uint32_t*)(smem + AP_L + off) = *(uint32_t*)&tl;
                }
            }
        }
        __syncwarp();

#pragma unroll
        for (int ko4 = 0; ko4 < 4; ko4++) {
            uint32_t ph[4], pl[4];
            {
                int arow = w * 16 + (lane & 15);
                uint32_t acb = (uint32_t)(ko4 * 32 + ((lane >> 4) << 4));
                uint32_t aoff = (uint32_t)(arow * 128) + (acb ^ ((uint32_t)(arow & 7) << 4));
                ldsm4(ph, sb + AP_H + aoff);
                ldsm4(pl, sb + AP_L + aoff);
            }
#pragma unroll
            for (int nj = 0; nj < 4; nj++) {
                int brow = ko4 * 16 + (lane & 7) + (((lane >> 3) & 1) << 3);
                uint32_t bcb = (uint32_t)(nj * 32 + ((lane >> 4) << 4));
                uint32_t boff = (uint32_t)(brow * 128) + (bcb ^ ((uint32_t)(brow & 7) << 4));
                uint32_t vh[4], vl[4];
                ldsm4t(vh, sb + AV_H + boff);
                ldsm4t(vl, sb + AV_L + boff);
#pragma unroll
                for (int hh = 0; hh < 2; hh++) {
                    const int j = nj * 2 + hh;
                    mma16816(oacc[j], ph, vh[hh*2], vh[hh*2+1]);
                    mma16816(oacc[j], ph, vl[hh*2], vl[hh*2+1]);
                    mma16816(oacc[j], pl, vh[hh*2], vh[hh*2+1]);
                }
            }
        }
    }

    float* attp = g_attp[half];
#pragma unroll
    for (int rr = 0; rr < 2; rr++) {
        int row  = w * 16 + (lane >> 2) + rr * 8;
        int grow = b * Tn + q0 + row;
        long gbase = (long)grow * Dn + h * 64;
#pragma unroll
        for (int j = 0; j < 8; j++) {
            int c = j * 8 + 2 * (lane & 3);
            *(float2*)(attp + gbase + c) = make_float2(oacc[j][rr*2], oacc[j][rr*2+1]);
        }
        if ((lane & 3) == 0) {
            g_pm[half][grow * 4 + h] = m_i[rr];
            g_pl[half][grow * 4 + h] = l_i[rr];
        }
    }
}

// ---------------------------------------------------------------------------
// Combine split-KV partials -> bf16 hi/lo activations.
// Reads ONLY partials p <= qt (others were never written this layer).
// ---------------------------------------------------------------------------
__global__ void attn_combine()
{
    int idx = blockIdx.x * 256 + threadIdx.x;
    int row = idx >> 6;
    int dq  = (idx & 63) << 2;
    int h   = dq >> 6;
    int qt  = (row & (Tn - 1)) >> 6;
    int np  = (qt < NSPLIT - 1) ? (qt + 1) : NSPLIT;

    float m = -1e30f;
    for (int p = 0; p < np; p++) m = fmaxf(m, g_pm[p][row * 4 + h]);
    float lsum = 0.f;
    float v0 = 0.f, v1 = 0.f, v2 = 0.f, v3 = 0.f;
    long base = (long)row * Dn + dq;
    for (int p = 0; p < np; p++) {
        float c = ex2f(g_pm[p][row * 4 + h] - m);
        lsum = fmaf(g_pl[p][row * 4 + h], c, lsum);
        float4 pv = *(float4*)(g_attp[p] + base);
        v0 = fmaf(pv.x, c, v0);
        v1 = fmaf(pv.y, c, v1);
        v2 = fmaf(pv.z, c, v2);
        v3 = fmaf(pv.w, c, v3);
    }
    float inv = 1.f / lsum;
    v0 *= inv; v1 *= inv; v2 *= inv; v3 *= inv;
    __nv_bfloat16 h0,h1,h2,h3,l0b,l1b,l2b,l3b;
    split1(v0,h0,l0b); split1(v1,h1,l1b); split1(v2,h2,l2b); split1(v3,h3,l3b);
    *(__nv_bfloat162*)(g_acth + base)     = __nv_bfloat162(h0, h1);
    *(__nv_bfloat162*)(g_acth + base + 2) = __nv_bfloat162(h2, h3);
    *(__nv_bfloat162*)(g_actl + base)     = __nv_bfloat162(l0b, l1b);
    *(__nv_bfloat162*)(g_actl + base + 2) = __nv_bfloat162(l2b, l3b);
}

// ---------------------------------------------------------------------------
// LayerNorm: x = LN(x [+ g_tmp]) * sc + bi ; writes x fp32 AND hi/lo bf16.
// ---------------------------------------------------------------------------
template<int ADD>
__device__ __forceinline__ void ln_body(const float* __restrict__ sc,
                                        const float* __restrict__ bi)
{
    int row  = blockIdx.x * 8 + (threadIdx.x >> 5);
    int lane = threadIdx.x & 31;
    const float* pa = g_x + (long)row * Dn + lane * 8;
    float v[8];
    {
        float4 v0 = *(const float4*)pa;
        float4 v1 = *(const float4*)(pa + 4);
        v[0] = v0.x; v[1] = v0.y; v[2] = v0.z; v[3] = v0.w;
        v[4] = v1.x; v[5] = v1.y; v[6] = v1.z; v[7] = v1.w;
    }
    if (ADD) {
        const float* pr = g_tmp + (long)row * Dn + lane * 8;
        float4 r0 = *(const float4*)pr;
        float4 r1 = *(const float4*)(pr + 4);
        v[0] += r0.x; v[1] += r0.y; v[2] += r0.z; v[3] += r0.w;
        v[4] += r1.x; v[5] += r1.y; v[6] += r1.z; v[7] += r1.w;
    }
    float s = 0.f;
#pragma unroll
    for (int k = 0; k < 8; k++) s += v[k];
#pragma unroll
    for (int ofs = 16; ofs; ofs >>= 1) s += __shfl_xor_sync(0xffffffffu, s, ofs);
    float mu = s * (1.f / 256.f);
    float var = 0.f;
#pragma unroll
    for (int k = 0; k < 8; k++) { float d = v[k] - mu; var = fmaf(d, d, var); }
#pragma unroll
    for (int ofs = 16; ofs; ofs >>= 1) var += __shfl_xor_sync(0xffffffffu, var, ofs);
    float rstd = rsqrtf(var * (1.f / 256.f) + 1e-5f);

    float4 s0 = *(const float4*)(sc + lane * 8);
    float4 s1 = *(const float4*)(sc + lane * 8 + 4);
    float4 b0 = *(const float4*)(bi + lane * 8);
    float4 b1 = *(const float4*)(bi + lane * 8 + 4);
    float scv[8] = {s0.x, s0.y, s0.z, s0.w, s1.x, s1.y, s1.z, s1.w};
    float biv[8] = {b0.x, b0.y, b0.z, b0.w, b1.x, b1.y, b1.z, b1.w};
    float o[8];
    __nv_bfloat16 oh[8], ol[8];
#pragma unroll
    for (int k = 0; k < 8; k++) {
        o[k] = fmaf((v[k] - mu) * rstd, scv[k], biv[k]);
        split1(o[k], oh[k], ol[k]);
    }
    long base = (long)row * Dn + lane * 8;
    *(float4*)(g_x + base)     = make_float4(o[0], o[1], o[2], o[3]);
    *(float4*)(g_x + base + 4) = make_float4(o[4], o[5], o[6], o[7]);
#pragma unroll
    for (int k = 0; k < 4; k++) {
        ((__nv_bfloat162*)(g_acth + base))[k] = __nv_bfloat162(oh[2*k], oh[2*k+1]);
        ((__nv_bfloat162*)(g_actl + base))[k] = __nv_bfloat162(ol[2*k], ol[2*k+1]);
    }
}
__global__ void add_ln_kernel(const float* sc, const float* bi) { ln_body<1>(sc, bi); }
__global__ void final_ln_kernel(const float* sc, const float* bi) { ln_body<0>(sc, bi); }

// ---------------------------------------------------------------------------
// Orchestration
// ---------------------------------------------------------------------------
extern "C" void kernel_launch(void* const* d_in, const int* in_sizes, int n_in,
                              void* d_out, int out_size)
{
    const int*   tokens = (const int*)d_in[0];
    const float* embedw = (const float*)d_in[1];
    const float* qkv_w  = (const float*)d_in[2];
    const float* qkv_b  = (const float*)d_in[3];
    const float* fc_w   = (const float*)d_in[4];
    const float* fc_b   = (const float*)d_in[5];
    const float* ln1_s  = (const float*)d_in[6];
    const float* ln1_b  = (const float*)d_in[7];
    const float* w1     = (const float*)d_in[8];
    const float* b1     = (const float*)d_in[9];
    const float* w2     = (const float*)d_in[10];
    const float* b2     = (const float*)d_in[11];
    const float* ln2_s  = (const float*)d_in[12];
    const float* ln2_b  = (const float*)d_in[13];
    const float* lnf_s  = (const float*)d_in[14];
    const float* lnf_b  = (const float*)d_in[15];
    const float* out_w  = (const float*)d_in[16];
    const float* out_b  = (const float*)d_in[17];
    float* logits = (float*)d_out;

    cudaFuncSetAttribute((const void*)gemm_qkv_tc,
        cudaFuncAttributeMaxDynamicSharedMemorySize, GSMEM64);
    cudaFuncSetAttribute((const void*)gemm_fc_tc,
        cudaFuncAttributeMaxDynamicSharedMemorySize, GSMEM32);
    cudaFuncSetAttribute((const void*)gemm_w1_tc,
        cudaFuncAttributeMaxDynamicSharedMemorySize, GSMEM64);
    cudaFuncSetAttribute((const void*)gemm_w2_tc,
        cudaFuncAttributeMaxDynamicSharedMemorySize, GSMEM32);
    cudaFuncSetAttribute((const void*)gemm_logits_tc,
        cudaFuncAttributeMaxDynamicSharedMemorySize, GSMEM64);
    cudaFuncSetAttribute((const void*)attn_kernel,
        cudaFuncAttributeMaxDynamicSharedMemorySize, ASMEM);

    split_weights<<<2048, 256>>>(qkv_w, fc_w, w1, w2, out_w);
    embed_pos_kernel<<<Mrows, Dn>>>(tokens, embedw);

    for (int l = 0; l < 4; l++) {
        gemm_qkv_tc<<<dim3(6, 64), 256, GSMEM64>>>(l, qkv_b + l * 768);
        attn_kernel<<<dim3(32, Bn * 4, NSPLIT), 128, ASMEM>>>();
        attn_combine<<<1024, 256>>>();
        gemm_fc_tc<<<dim3(2, 128), 128, GSMEM32>>>(l, fc_b + l * 256);
        add_ln_kernel<<<Mrows / 8, 256>>>(ln1_s + l * 256, ln1_b + l * 256);
        gemm_w1_tc<<<dim3(8, 64), 256, GSMEM64>>>(l, b1 + l * 1024);
        gemm_w2_tc<<<dim3(2, 128), 128, GSMEM32>>>(l, b2 + l * 256);
        add_ln_kernel<<<Mrows / 8, 256>>>(ln2_s + l * 256, ln2_b + l * 256);
    }
    final_ln_kernel<<<Mrows / 8, 256>>>(lnf_s, lnf_b);
    gemm_logits_tc<<<dim3(250, 64), 256, GSMEM64>>>(out_b, logits);
}

// round 15
// speedup vs baseline: 1.0259x; 1.0078x over previous
#include <cuda_runtime.h>
#include <cuda_bf16.h>
#include <math.h>
#include <stdint.h>

// ---------------------------------------------------------------------------
// MiniGPT forward. B=2 T=2048 D=256 H=4 DK=64 DFF=1024 L=4 V=32000
// GEMMs: mma.sync bf16x3. qkv/w1/logits TM=64, fc/w2 TM=32.
// Attention: HMMA flash, split-KV x8, MUFU ex2 softmax, P kept in registers
// (C-frag == A-frag identity; no smem round trip), 48KB smem -> 4 CTAs/SM.
// ---------------------------------------------------------------------------

#define Tn    2048
#define Bn    2
#define Dn    256
#define Mrows 4096
#define NSPLIT 8

// fp32 scratch
__device__ float g_x[Mrows * Dn];
__device__ float g_tmp[Mrows * Dn];

// attention split-KV partials
__device__ float g_attp[NSPLIT][Mrows * Dn];
__device__ float g_pm[NSPLIT][Mrows * 4];
__device__ float g_pl[NSPLIT][Mrows * 4];

// bf16 hi/lo activations, qkv, MLP hidden
__device__ __nv_bfloat16 g_acth[Mrows * Dn],  g_actl[Mrows * Dn];
__device__ __nv_bfloat16 g_qkvh[Mrows * 768], g_qkvl[Mrows * 768];
__device__ __nv_bfloat16 g_hh[Mrows * 1024],  g_hl[Mrows * 1024];

// bf16 hi/lo weights
__device__ __nv_bfloat16 g_wqkv_h[4 * 768 * 256],  g_wqkv_l[4 * 768 * 256];
__device__ __nv_bfloat16 g_wfc_h [4 * 256 * 256],  g_wfc_l [4 * 256 * 256];
__device__ __nv_bfloat16 g_w1_h  [4 * 1024 * 256], g_w1_l  [4 * 1024 * 256];
__device__ __nv_bfloat16 g_w2_h  [4 * 256 * 1024], g_w2_l  [4 * 256 * 1024];
__device__ __nv_bfloat16 g_wout_h[32000 * 256],    g_wout_l[32000 * 256];

// ---------------------------------------------------------------------------
// PTX helpers
// ---------------------------------------------------------------------------
__device__ __forceinline__ uint32_t smem_to_u32(const void* p) {
    uint32_t a;
    asm("{ .reg .u64 t; cvta.to.shared.u64 t, %1; cvt.u32.u64 %0, t; }"
        : "=r"(a) : "l"(p));
    return a;
}
__device__ __forceinline__ void ldsm4(uint32_t* r, uint32_t addr) {
    asm volatile("ldmatrix.sync.aligned.m8n8.x4.shared.b16 {%0,%1,%2,%3}, [%4];"
                 : "=r"(r[0]), "=r"(r[1]), "=r"(r[2]), "=r"(r[3]) : "r"(addr));
}
__device__ __forceinline__ void ldsm4t(uint32_t* r, uint32_t addr) {
    asm volatile("ldmatrix.sync.aligned.m8n8.x4.trans.shared.b16 {%0,%1,%2,%3}, [%4];"
                 : "=r"(r[0]), "=r"(r[1]), "=r"(r[2]), "=r"(r[3]) : "r"(addr));
}
__device__ __forceinline__ void mma16816(float* d, const uint32_t* a,
                                         uint32_t b0, uint32_t b1) {
    asm volatile(
        "mma.sync.aligned.m16n8k16.row.col.f32.bf16.bf16.f32 "
        "{%0,%1,%2,%3}, {%4,%5,%6,%7}, {%8,%9}, {%0,%1,%2,%3};"
        : "+f"(d[0]), "+f"(d[1]), "+f"(d[2]), "+f"(d[3])
        : "r"(a[0]), "r"(a[1]), "r"(a[2]), "r"(a[3]), "r"(b0), "r"(b1));
}
__device__ __forceinline__ float ex2f(float x) {
    float y;
    asm("ex2.approx.f32 %0, %1;" : "=f"(y) : "f"(x));
    return y;
}
#define CP_ASYNC16(dst, src) \
    asm volatile("cp.async.cg.shared.global [%0], [%1], 16;" \
                 :: "r"(dst), "l"(src) : "memory")
#define CP_COMMIT()  asm volatile("cp.async.commit_group;" ::: "memory")
#define CP_WAIT0()   asm volatile("cp.async.wait_group 0;" ::: "memory")

__device__ __forceinline__ void split1(float v, __nv_bfloat16& h, __nv_bfloat16& l) {
    h = __float2bfloat16(v);
    l = __float2bfloat16(v - __bfloat162float(h));
}
__device__ __forceinline__ uint32_t pack2(__nv_bfloat16 a, __nv_bfloat16 b) {
    __nv_bfloat162 t(a, b);
    return *(uint32_t*)&t;
}

// ---------------------------------------------------------------------------
// Fused weight split
// ---------------------------------------------------------------------------
__global__ void split_weights(const float* __restrict__ qkv_w,
                              const float* __restrict__ fc_w,
                              const float* __restrict__ w1,
                              const float* __restrict__ w2,
                              const float* __restrict__ out_w)
{
    const int c0 = 196608, c1 = c0 + 65536, c2 = c1 + 262144,
              c3 = c2 + 262144, c4 = c3 + 2048000;
    int stride = gridDim.x * blockDim.x;
    for (int idx = blockIdx.x * blockDim.x + threadIdx.x; idx < c4; idx += stride) {
        const float* src; __nv_bfloat16 *dh, *dl; int li;
        if (idx < c0)      { src = qkv_w; dh = g_wqkv_h; dl = g_wqkv_l; li = idx; }
        else if (idx < c1) { src = fc_w;  dh = g_wfc_h;  dl = g_wfc_l;  li = idx - c0; }
        else if (idx < c2) { src = w1;    dh = g_w1_h;   dl = g_w1_l;   li = idx - c1; }
        else if (idx < c3) { src = w2;    dh = g_w2_h;   dl = g_w2_l;   li = idx - c2; }
        else               { src = out_w; dh = g_wout_h; dl = g_wout_l; li = idx - c3; }
        float4 v = ((const float4*)src)[li];
        __nv_bfloat16 h0, h1, h2, h3, l0, l1, l2, l3;
        split1(v.x, h0, l0); split1(v.y, h1, l1);
        split1(v.z, h2, l2); split1(v.w, h3, l3);
        ((__nv_bfloat162*)dh)[li * 2 + 0] = __nv_bfloat162(h0, h1);
        ((__nv_bfloat162*)dh)[li * 2 + 1] = __nv_bfloat162(h2, h3);
        ((__nv_bfloat162*)dl)[li * 2 + 0] = __nv_bfloat162(l0, l1);
        ((__nv_bfloat162*)dl)[li * 2 + 1] = __nv_bfloat162(l2, l3);
    }
}

// ---------------------------------------------------------------------------
// mma.sync bf16x3 GEMM. TM in {64, 32}, TN = 128. (unchanged)
// ---------------------------------------------------------------------------
#define GSMEM64  (2 * 49152)
#define GSMEM32  (2 * 40960)

template<int TM, int N, int K, int RELU, int WSPLIT>
__device__ __forceinline__ void gemm_body(
    const __nv_bfloat16* __restrict__ Ah, const __nv_bfloat16* __restrict__ Al,
    const __nv_bfloat16* __restrict__ Bh, const __nv_bfloat16* __restrict__ Bl,
    const float* __restrict__ bias, float* __restrict__ C,
    __nv_bfloat16* __restrict__ Ch, __nv_bfloat16* __restrict__ Cl)
{
    extern __shared__ char smem[];
    const uint32_t sb = smem_to_u32(smem);
    const int tid  = threadIdx.x;
    const int wid  = tid >> 5;
    const int lane = tid & 31;
    const int m0   = blockIdx.y * TM;
    const int n0   = blockIdx.x << 7;
    constexpr int NST   = K / 64;
    constexpr int STAGE = (TM == 64) ? 49152 : 40960;
    constexpr int AOFF  = (TM == 64) ? 8192 : 4096;
    constexpr int BOFF  = (TM == 64) ? 16384 : 8192;
    constexpr int BSZ   = 16384;
    const int wr = (TM == 64) ? (wid & 1) : 0;
    const int wc = (TM == 64) ? (wid >> 1) : wid;

    float acc[2][4][4];
#pragma unroll
    for (int i = 0; i < 2; i++)
#pragma unroll
        for (int j = 0; j < 4; j++)
#pragma unroll
            for (int q = 0; q < 4; q++) acc[i][j][q] = 0.f;

    const int q = tid >> 3;
    uint32_t cbyte = (uint32_t)((tid & 7) << 4);
    const uint32_t swq = cbyte ^ (uint32_t)((q & 7) << 4);
    const uint32_t dq  = (uint32_t)q;
    const int ce = (tid & 7) << 3;
    const __nv_bfloat16* pah = Ah + (long)(m0 + q) * K + ce;
    const __nv_bfloat16* pal = Al + (long)(m0 + q) * K + ce;
    const __nv_bfloat16* pbh = Bh + (long)(n0 + q) * K + ce;
    const __nv_bfloat16* pbl = Bl + (long)(n0 + q) * K + ce;
    constexpr int RSTRIDE = (TM == 64) ? 32 : 16;
    constexpr int AU = 2;
    constexpr int BU = (TM == 64) ? 4 : 8;

#define LOAD_STAGE(sbuf, koff)                                                  \
    do {                                                                        \
        uint32_t base = sb + (sbuf) * (uint32_t)STAGE;                          \
        _Pragma("unroll")                                                       \
        for (int u = 0; u < AU; u++) {                                          \
            uint32_t row = dq + u * RSTRIDE;                                    \
            CP_ASYNC16(base + row * 128 + swq,                                  \
                       (const char*)(pah + (long)u * RSTRIDE * K + (koff)));    \
            CP_ASYNC16(base + AOFF + row * 128 + swq,                           \
                       (const char*)(pal + (long)u * RSTRIDE * K + (koff)));    \
        }                                                                       \
        _Pragma("unroll")                                                       \
        for (int u = 0; u < BU; u++) {                                          \
            uint32_t row = dq + u * RSTRIDE;                                    \
            CP_ASYNC16(base + BOFF + row * 128 + swq,                           \
                       (const char*)(pbh + (long)u * RSTRIDE * K + (koff)));    \
            CP_ASYNC16(base + BOFF + BSZ + row * 128 + swq,                     \
                       (const char*)(pbl + (long)u * RSTRIDE * K + (koff)));    \
        }                                                                       \
        CP_COMMIT();                                                            \
    } while (0)

    LOAD_STAGE(0, 0);

    for (int s = 0; s < NST; s++) {
        CP_WAIT0();
        __syncthreads();
        if (s + 1 < NST) LOAD_STAGE((s + 1) & 1, (s + 1) * 64);
        const uint32_t bufb = sb + (uint32_t)((s & 1) * STAGE);

#pragma unroll
        for (int ko = 0; ko < 64; ko += 16) {
            uint32_t afr[2][2][4];
            uint32_t bfr[2][2][4];
            {
                const int rowb = wr * 32 + (lane & 15);
                const int cb   = ko * 2 + ((lane >> 4) << 4);
#pragma unroll
                for (int t = 0; t < 2; t++)
#pragma unroll
                    for (int mi = 0; mi < 2; mi++) {
                        int row = rowb + mi * 16;
                        uint32_t addr = bufb + (uint32_t)(t * AOFF) + row * 128
                                      + (uint32_t)(cb ^ ((row & 7) << 4));
                        ldsm4(afr[t][mi], addr);
                    }
            }
            {
                const int rowb = wc * 32 + (lane & 7) + ((lane >> 4) << 3);
                const int cb   = ko * 2 + (((lane >> 3) & 1) << 4);
#pragma unroll
                for (int t = 0; t < 2; t++)
#pragma unroll
                    for (int nj = 0; nj < 2; nj++) {
                        int row = rowb + nj * 16;
                        uint32_t addr = bufb + (uint32_t)BOFF + (uint32_t)(t * BSZ)
                                      + row * 128 + (uint32_t)(cb ^ ((row & 7) << 4));
                        ldsm4(bfr[t][nj], addr);
                    }
            }
#pragma unroll
            for (int mi = 0; mi < 2; mi++)
#pragma unroll
                for (int nj = 0; nj < 2; nj++)
#pragma unroll
                    for (int hh = 0; hh < 2; hh++) {
                        const int nc = nj * 2 + hh;
                        const uint32_t bh0 = bfr[0][nj][hh * 2];
                        const uint32_t bh1 = bfr[0][nj][hh * 2 + 1];
                        const uint32_t bl0 = bfr[1][nj][hh * 2];
                        const uint32_t bl1 = bfr[1][nj][hh * 2 + 1];
                        mma16816(acc[mi][nc], afr[0][mi], bh0, bh1);
                        mma16816(acc[mi][nc], afr[0][mi], bl0, bl1);
                        mma16816(acc[mi][nc], afr[1][mi], bh0, bh1);
                    }
        }
        __syncthreads();
    }
#undef LOAD_STAGE

#pragma unroll
    for (int mi = 0; mi < 2; mi++)
#pragma unroll
        for (int nc = 0; nc < 4; nc++) {
            int row = m0 + wr * 32 + mi * 16 + (lane >> 2);
            int col = n0 + wc * 32 + nc * 8 + (lane & 3) * 2;
            float b0v = bias[col], b1v = bias[col + 1];
            float v0 = acc[mi][nc][0] + b0v;
            float v1 = acc[mi][nc][1] + b1v;
            float v2 = acc[mi][nc][2] + b0v;
            float v3 = acc[mi][nc][3] + b1v;
            if (RELU) {
                v0 = fmaxf(v0, 0.f); v1 = fmaxf(v1, 0.f);
                v2 = fmaxf(v2, 0.f); v3 = fmaxf(v3, 0.f);
            }
            if (WSPLIT) {
                __nv_bfloat16 h0, h1, h2, h3, l0, l1, l2, l3;
                split1(v0, h0, l0); split1(v1, h1, l1);
                split1(v2, h2, l2); split1(v3, h3, l3);
                *(__nv_bfloat162*)(Ch + (long)row * N + col)       = __nv_bfloat162(h0, h1);
                *(__nv_bfloat162*)(Ch + (long)(row + 8) * N + col) = __nv_bfloat162(h2, h3);
                *(__nv_bfloat162*)(Cl + (long)row * N + col)       = __nv_bfloat162(l0, l1);
                *(__nv_bfloat162*)(Cl + (long)(row + 8) * N + col) = __nv_bfloat162(l2, l3);
            } else {
                *(float2*)(C + (long)row * N + col)       = make_float2(v0, v1);
                *(float2*)(C + (long)(row + 8) * N + col) = make_float2(v2, v3);
            }
        }
}

__global__ __launch_bounds__(256) void gemm_qkv_tc(int l, const float* bias)
{ gemm_body<64, 768, 256, 0, 1>(g_acth, g_actl, g_wqkv_h + l*196608, g_wqkv_l + l*196608,
                                bias, nullptr, g_qkvh, g_qkvl); }
__global__ __launch_bounds__(128) void gemm_fc_tc(int l, const float* bias)
{ gemm_body<32, 256, 256, 0, 0>(g_acth, g_actl, g_wfc_h + l*65536, g_wfc_l + l*65536,
                                bias, g_tmp, nullptr, nullptr); }
__global__ __launch_bounds__(256) void gemm_w1_tc(int l, const float* bias)
{ gemm_body<64, 1024, 256, 1, 1>(g_acth, g_actl, g_w1_h + l*262144, g_w1_l + l*262144,
                                 bias, nullptr, g_hh, g_hl); }
__global__ __launch_bounds__(128) void gemm_w2_tc(int l, const float* bias)
{ gemm_body<32, 256, 1024, 0, 0>(g_hh, g_hl, g_w2_h + l*262144, g_w2_l + l*262144,
                                 bias, g_tmp, nullptr, nullptr); }
__global__ __launch_bounds__(256) void gemm_logits_tc(const float* bias, float* out)
{ gemm_body<64, 32000, 256, 0, 0>(g_acth, g_actl, g_wout_h, g_wout_l,
                                  bias, out, nullptr, nullptr); }

// ---------------------------------------------------------------------------
// Embedding + positional encoding
// ---------------------------------------------------------------------------
__global__ void embed_pos_kernel(const int* __restrict__ tok,
                                 const float* __restrict__ emb)
{
    int row = blockIdx.x;
    int d   = threadIdx.x;
    int t   = row & (Tn - 1);
    int token = tok[row];
    double div = exp(-(double)(d & ~1) * (9.210340371976184 / 256.0));
    double ang = (double)t * div;
    float  pe  = (d & 1) ? (float)cos(ang) : (float)sin(ang);
    float v = emb[token * Dn + d] + pe;
    g_x[row * Dn + d] = v;
    __nv_bfloat16 h, l;
    split1(v, h, l);
    g_acth[row * Dn + d] = h;
    g_actl[row * Dn + d] = l;
}

// ---------------------------------------------------------------------------
// HMMA flash attention, split-KV x8, MUFU ex2 softmax. P stays in registers:
// m16n8k16 C-frag(j0,j1) == A-frag(k chunk) identity (FA2 trick).
// smem 48KB: QH 0 | QL 8K | KH 16K | KL 24K | VH 32K | VL 40K -> 4 CTAs/SM.
// ---------------------------------------------------------------------------
#define AQ_H  0
#define AQ_L  8192
#define AK_H  16384
#define AK_L  24576
#define AV_H  32768
#define AV_L  40960
#define ASMEM 49152
#define QSCALE 0.18033688f    /* 0.125 * log2(e) */

__global__ __launch_bounds__(128) void attn_kernel()
{
    extern __shared__ char smem[];
    const uint32_t sb = smem_to_u32(smem);
    const int tid  = threadIdx.x;
    const int lane = tid & 31;
    const int w    = tid >> 5;
    const int qt   = blockIdx.x;
    const int b    = blockIdx.y >> 2;
    const int h    = blockIdx.y & 3;
    const int half = blockIdx.z;
    const int q0   = qt << 6;

    const int nst = (qt >= half) ? ((qt - half) / NSPLIT + 1) : 0;
    if (nst == 0) return;

    const __nv_bfloat16* bh_ = g_qkvh + (long)b * Tn * 768 + h * 64;
    const __nv_bfloat16* bl_ = g_qkvl + (long)b * Tn * 768 + h * 64;

    const int lr  = tid & 63;
    const int cb0 = (tid >> 6) * 4;

    {
        const __nv_bfloat16* qh = bh_ + (long)(q0 + lr) * 768;
        const __nv_bfloat16* ql = bl_ + (long)(q0 + lr) * 768;
#pragma unroll
        for (int c = cb0; c < cb0 + 4; c++) {
            uint32_t off = (uint32_t)(lr * 128) + (uint32_t)((c * 16) ^ ((lr & 7) << 4));
            CP_ASYNC16(sb + AQ_H + off, qh + c * 8);
            CP_ASYNC16(sb + AQ_L + off, ql + c * 8);
        }
        CP_COMMIT();
    }

    float m_i[2] = {-1e30f, -1e30f};
    float l_i[2] = {0.f, 0.f};
    float oacc[8][4];
#pragma unroll
    for (int j = 0; j < 8; j++)
#pragma unroll
        for (int q = 0; q < 4; q++) oacc[j][q] = 0.f;

    for (int s = 0; s < nst; s++) {
        const int kt = half + NSPLIT * s;
        const int k0 = kt << 6;
        __syncthreads();
        {
            const __nv_bfloat16* kh = bh_ + (long)(k0 + lr) * 768 + 256;
            const __nv_bfloat16* kl = bl_ + (long)(k0 + lr) * 768 + 256;
            const __nv_bfloat16* vh = bh_ + (long)(k0 + lr) * 768 + 512;
            const __nv_bfloat16* vl = bl_ + (long)(k0 + lr) * 768 + 512;
#pragma unroll
            for (int c = cb0; c < cb0 + 4; c++) {
                uint32_t off = (uint32_t)(lr * 128)
                             + (uint32_t)((c * 16) ^ ((lr & 7) << 4));
                CP_ASYNC16(sb + AK_H + off, kh + c * 8);
                CP_ASYNC16(sb + AK_L + off, kl + c * 8);
                CP_ASYNC16(sb + AV_H + off, vh + c * 8);
                CP_ASYNC16(sb + AV_L + off, vl + c * 8);
            }
            CP_COMMIT();
        }
        CP_WAIT0();
        __syncthreads();

        float sacc[8][4];
#pragma unroll
        for (int j = 0; j < 8; j++)
#pragma unroll
            for (int q = 0; q < 4; q++) sacc[j][q] = 0.f;

#pragma unroll
        for (int ko4 = 0; ko4 < 4; ko4++) {
            uint32_t ah[4], al[4];
            {
                int arow = w * 16 + (lane & 15);
                uint32_t acb = (uint32_t)(ko4 * 32 + ((lane >> 4) << 4));
                uint32_t aoff = (uint32_t)(arow * 128) + (acb ^ ((uint32_t)(arow & 7) << 4));
                ldsm4(ah, sb + AQ_H + aoff);
                ldsm4(al, sb + AQ_L + aoff);
            }
#pragma unroll
            for (int nj = 0; nj < 4; nj++) {
                int brow = nj * 16 + (lane & 7) + ((lane >> 4) << 3);
                uint32_t bcb = (uint32_t)(ko4 * 32 + (((lane >> 3) & 1) << 4));
                uint32_t boff = (uint32_t)(brow * 128) + (bcb ^ ((uint32_t)(brow & 7) << 4));
                uint32_t bh[4], bl[4];
                ldsm4(bh, sb + AK_H + boff);
                ldsm4(bl, sb + AK_L + boff);
#pragma unroll
                for (int hh = 0; hh < 2; hh++) {
                    const int j = nj * 2 + hh;
                    mma16816(sacc[j], ah, bh[hh*2], bh[hh*2+1]);
                    mma16816(sacc[j], ah, bl[hh*2], bl[hh*2+1]);
                    mma16816(sacc[j], al, bh[hh*2], bh[hh*2+1]);
                }
            }
        }

#pragma unroll
        for (int j = 0; j < 8; j++)
#pragma unroll
            for (int q = 0; q < 4; q++) sacc[j][q] *= QSCALE;

        if (kt == qt) {
            const int r0 = lane >> 2;
            const int c0 = 2 * (lane & 3);
#pragma unroll
            for (int j = 0; j < 8; j++) {
                int c = j * 8 + c0;
                int rowA = w * 16 + r0;
                int rowB = rowA + 8;
                if (c     > rowA) sacc[j][0] = -1e30f;
                if (c + 1 > rowA) sacc[j][1] = -1e30f;
                if (c     > rowB) sacc[j][2] = -1e30f;
                if (c + 1 > rowB) sacc[j][3] = -1e30f;
            }
        }

#pragma unroll
        for (int rr = 0; rr < 2; rr++) {
            float mx = -1e30f;
#pragma unroll
            for (int j = 0; j < 8; j++)
                mx = fmaxf(mx, fmaxf(sacc[j][rr*2], sacc[j][rr*2+1]));
            mx = fmaxf(mx, __shfl_xor_sync(0xffffffffu, mx, 1));
            mx = fmaxf(mx, __shfl_xor_sync(0xffffffffu, mx, 2));
            float mn   = fmaxf(m_i[rr], mx);
            float corr = ex2f(m_i[rr] - mn);
            float rs = 0.f;
#pragma unroll
            for (int j = 0; j < 8; j++) {
                float p0 = ex2f(sacc[j][rr*2]   - mn);
                float p1 = ex2f(sacc[j][rr*2+1] - mn);
                sacc[j][rr*2] = p0; sacc[j][rr*2+1] = p1;
                rs += p0 + p1;
            }
            rs += __shfl_xor_sync(0xffffffffu, rs, 1);
            rs += __shfl_xor_sync(0xffffffffu, rs, 2);
            l_i[rr] = l_i[rr] * corr + rs;
            m_i[rr] = mn;
#pragma unroll
            for (int j = 0; j < 8; j++) {
                oacc[j][rr*2]   *= corr;
                oacc[j][rr*2+1] *= corr;
            }
        }

        // ---- O += P V : P A-frags built directly from sacc (C==A identity) -
#pragma unroll
        for (int ko4 = 0; ko4 < 4; ko4++) {
            uint32_t ph[4], pl[4];
            {
                const int j0 = ko4 * 2, j1 = j0 + 1;
                __nv_bfloat16 h0, l0, h1, l1;
                split1(sacc[j0][0], h0, l0); split1(sacc[j0][1], h1, l1);
                ph[0] = pack2(h0, h1); pl[0] = pack2(l0, l1);
                split1(sacc[j0][2], h0, l0); split1(sacc[j0][3], h1, l1);
                ph[1] = pack2(h0, h1); pl[1] = pack2(l0, l1);
                split1(sacc[j1][0], h0, l0); split1(sacc[j1][1], h1, l1);
                ph[2] = pack2(h0, h1); pl[2] = pack2(l0, l1);
                split1(sacc[j1][2], h0, l0); split1(sacc[j1][3], h1, l1);
                ph[3] = pack2(h0, h1); pl[3] = pack2(l0, l1);
            }
#pragma unroll
            for (int nj = 0; nj < 4; nj++) {
                int brow = ko4 * 16 + (lane & 7) + (((lane >> 3) & 1) << 3);
                uint32_t bcb = (uint32_t)(nj * 32 + ((lane >> 4) << 4));
                uint32_t boff = (uint32_t)(brow * 128) + (bcb ^ ((uint32_t)(brow & 7) << 4));
                uint32_t vh[4], vl[4];
                ldsm4t(vh, sb + AV_H + boff);
                ldsm4t(vl, sb + AV_L + boff);
#pragma unroll
                for (int hh = 0; hh < 2; hh++) {
                    const int j = nj * 2 + hh;
                    mma16816(oacc[j], ph, vh[hh*2], vh[hh*2+1]);
                    mma16816(oacc[j], ph, vl[hh*2], vl[hh*2+1]);
                    mma16816(oacc[j], pl, vh[hh*2], vh[hh*2+1]);
                }
            }
        }
    }

    float* attp = g_attp[half];
#pragma unroll
    for (int rr = 0; rr < 2; rr++) {
        int row  = w * 16 + (lane >> 2) + rr * 8;
        int grow = b * Tn + q0 + row;
        long gbase = (long)grow * Dn + h * 64;
#pragma unroll
        for (int j = 0; j < 8; j++) {
            int c = j * 8 + 2 * (lane & 3);
            *(float2*)(attp + gbase + c) = make_float2(oacc[j][rr*2], oacc[j][rr*2+1]);
        }
        if ((lane & 3) == 0) {
            g_pm[half][grow * 4 + h] = m_i[rr];
            g_pl[half][grow * 4 + h] = l_i[rr];
        }
    }
}

// ---------------------------------------------------------------------------
// Combine split-KV partials -> bf16 hi/lo activations (bounded by qt).
// ---------------------------------------------------------------------------
__global__ void attn_combine()
{
    int idx = blockIdx.x * 256 + threadIdx.x;
    int row = idx >> 6;
    int dq  = (idx & 63) << 2;
    int h   = dq >> 6;
    int qt  = (row & (Tn - 1)) >> 6;
    int np  = (qt < NSPLIT - 1) ? (qt + 1) : NSPLIT;

    float m = -1e30f;
    for (int p = 0; p < np; p++) m = fmaxf(m, g_pm[p][row * 4 + h]);
    float lsum = 0.f;
    float v0 = 0.f, v1 = 0.f, v2 = 0.f, v3 = 0.f;
    long base = (long)row * Dn + dq;
    for (int p = 0; p < np; p++) {
        float c = ex2f(g_pm[p][row * 4 + h] - m);
        lsum = fmaf(g_pl[p][row * 4 + h], c, lsum);
        float4 pv = *(float4*)(g_attp[p] + base);
        v0 = fmaf(pv.x, c, v0);
        v1 = fmaf(pv.y, c, v1);
        v2 = fmaf(pv.z, c, v2);
        v3 = fmaf(pv.w, c, v3);
    }
    float inv = 1.f / lsum;
    v0 *= inv; v1 *= inv; v2 *= inv; v3 *= inv;
    __nv_bfloat16 h0,h1,h2,h3,l0b,l1b,l2b,l3b;
    split1(v0,h0,l0b); split1(v1,h1,l1b); split1(v2,h2,l2b); split1(v3,h3,l3b);
    *(__nv_bfloat162*)(g_acth + base)     = __nv_bfloat162(h0, h1);
    *(__nv_bfloat162*)(g_acth + base + 2) = __nv_bfloat162(h2, h3);
    *(__nv_bfloat162*)(g_actl + base)     = __nv_bfloat162(l0b, l1b);
    *(__nv_bfloat162*)(g_actl + base + 2) = __nv_bfloat162(l2b, l3b);
}

// ---------------------------------------------------------------------------
// LayerNorm: x = LN(x [+ g_tmp]) * sc + bi ; writes x fp32 AND hi/lo bf16.
// ---------------------------------------------------------------------------
template<int ADD>
__device__ __forceinline__ void ln_body(const float* __restrict__ sc,
                                        const float* __restrict__ bi)
{
    int row  = blockIdx.x * 8 + (threadIdx.x >> 5);
    int lane = threadIdx.x & 31;
    const float* pa = g_x + (long)row * Dn + lane * 8;
    float v[8];
    {
        float4 v0 = *(const float4*)pa;
        float4 v1 = *(const float4*)(pa + 4);
        v[0] = v0.x; v[1] = v0.y; v[2] = v0.z; v[3] = v0.w;
        v[4] = v1.x; v[5] = v1.y; v[6] = v1.z; v[7] = v1.w;
    }
    if (ADD) {
        const float* pr = g_tmp + (long)row * Dn + lane * 8;
        float4 r0 = *(const float4*)pr;
        float4 r1 = *(const float4*)(pr + 4);
        v[0] += r0.x; v[1] += r0.y; v[2] += r0.z; v[3] += r0.w;
        v[4] += r1.x; v[5] += r1.y; v[6] += r1.z; v[7] += r1.w;
    }
    float s = 0.f;
#pragma unroll
    for (int k = 0; k < 8; k++) s += v[k];
#pragma unroll
    for (int ofs = 16; ofs; ofs >>= 1) s += __shfl_xor_sync(0xffffffffu, s, ofs);
    float mu = s * (1.f / 256.f);
    float var = 0.f;
#pragma unroll
    for (int k = 0; k < 8; k++) { float d = v[k] - mu; var = fmaf(d, d, var); }
#pragma unroll
    for (int ofs = 16; ofs; ofs >>= 1) var += __shfl_xor_sync(0xffffffffu, var, ofs);
    float rstd = rsqrtf(var * (1.f / 256.f) + 1e-5f);

    float4 s0 = *(const float4*)(sc + lane * 8);
    float4 s1 = *(const float4*)(sc + lane * 8 + 4);
    float4 b0 = *(const float4*)(bi + lane * 8);
    float4 b1 = *(const float4*)(bi + lane * 8 + 4);
    float scv[8] = {s0.x, s0.y, s0.z, s0.w, s1.x, s1.y, s1.z, s1.w};
    float biv[8] = {b0.x, b0.y, b0.z, b0.w, b1.x, b1.y, b1.z, b1.w};
    float o[8];
    __nv_bfloat16 oh[8], ol[8];
#pragma unroll
    for (int k = 0; k < 8; k++) {
        o[k] = fmaf((v[k] - mu) * rstd, scv[k], biv[k]);
        split1(o[k], oh[k], ol[k]);
    }
    long base = (long)row * Dn + lane * 8;
    *(float4*)(g_x + base)     = make_float4(o[0], o[1], o[2], o[3]);
    *(float4*)(g_x + base + 4) = make_float4(o[4], o[5], o[6], o[7]);
#pragma unroll
    for (int k = 0; k < 4; k++) {
        ((__nv_bfloat162*)(g_acth + base))[k] = __nv_bfloat162(oh[2*k], oh[2*k+1]);
        ((__nv_bfloat162*)(g_actl + base))[k] = __nv_bfloat162(ol[2*k], ol[2*k+1]);
    }
}
__global__ void add_ln_kernel(const float* sc, const float* bi) { ln_body<1>(sc, bi); }
__global__ void final_ln_kernel(const float* sc, const float* bi) { ln_body<0>(sc, bi); }

// ---------------------------------------------------------------------------
// Orchestration
// ---------------------------------------------------------------------------
extern "C" void kernel_launch(void* const* d_in, const int* in_sizes, int n_in,
                              void* d_out, int out_size)
{
    const int*   tokens = (const int*)d_in[0];
    const float* embedw = (const float*)d_in[1];
    const float* qkv_w  = (const float*)d_in[2];
    const float* qkv_b  = (const float*)d_in[3];
    const float* fc_w   = (const float*)d_in[4];
    const float* fc_b   = (const float*)d_in[5];
    const float* ln1_s  = (const float*)d_in[6];
    const float* ln1_b  = (const float*)d_in[7];
    const float* w1     = (const float*)d_in[8];
    const float* b1     = (const float*)d_in[9];
    const float* w2     = (const float*)d_in[10];
    const float* b2     = (const float*)d_in[11];
    const float* ln2_s  = (const float*)d_in[12];
    const float* ln2_b  = (const float*)d_in[13];
    const float* lnf_s  = (const float*)d_in[14];
    const float* lnf_b  = (const float*)d_in[15];
    const float* out_w  = (const float*)d_in[16];
    const float* out_b  = (const float*)d_in[17];
    float* logits = (float*)d_out;

    cudaFuncSetAttribute((const void*)gemm_qkv_tc,
        cudaFuncAttributeMaxDynamicSharedMemorySize, GSMEM64);
    cudaFuncSetAttribute((const void*)gemm_fc_tc,
        cudaFuncAttributeMaxDynamicSharedMemorySize, GSMEM32);
    cudaFuncSetAttribute((const void*)gemm_w1_tc,
        cudaFuncAttributeMaxDynamicSharedMemorySize, GSMEM64);
    cudaFuncSetAttribute((const void*)gemm_w2_tc,
        cudaFuncAttributeMaxDynamicSharedMemorySize, GSMEM32);
    cudaFuncSetAttribute((const void*)gemm_logits_tc,
        cudaFuncAttributeMaxDynamicSharedMemorySize, GSMEM64);
    cudaFuncSetAttribute((const void*)attn_kernel,
        cudaFuncAttributeMaxDynamicSharedMemorySize, ASMEM);

    split_weights<<<2048, 256>>>(qkv_w, fc_w, w1, w2, out_w);
    embed_pos_kernel<<<Mrows, Dn>>>(tokens, embedw);

    for (int l = 0; l < 4; l++) {
        gemm_qkv_tc<<<dim3(6, 64), 256, GSMEM64>>>(l, qkv_b + l * 768);
        attn_kernel<<<dim3(32, Bn * 4, NSPLIT), 128, ASMEM>>>();
        attn_combine<<<1024, 256>>>();
        gemm_fc_tc<<<dim3(2, 128), 128, GSMEM32>>>(l, fc_b + l * 256);
        add_ln_kernel<<<Mrows / 8, 256>>>(ln1_s + l * 256, ln1_b + l * 256);
        gemm_w1_tc<<<dim3(8, 64), 256, GSMEM64>>>(l, b1 + l * 1024);
        gemm_w2_tc<<<dim3(2, 128), 128, GSMEM32>>>(l, b2 + l * 256);
        add_ln_kernel<<<Mrows / 8, 256>>>(ln2_s + l * 256, ln2_b + l * 256);
    }
    final_ln_kernel<<<Mrows / 8, 256>>>(lnf_s, lnf_b);
    gemm_logits_tc<<<dim3(250, 64), 256, GSMEM64>>>(out_b, logits);
}

// round 16
// speedup vs baseline: 1.0288x; 1.0028x over previous
#include <cuda_runtime.h>
#include <cuda_bf16.h>
#include <math.h>
#include <stdint.h>

// ---------------------------------------------------------------------------
// MiniGPT forward. B=2 T=2048 D=256 H=4 DK=64 DFF=1024 L=4 V=32000
// GEMMs: mma.sync bf16x3. qkv/w1/logits TM=64, fc/w2 TM=32.
// Attention: HMMA flash, split-KV x8, MUFU ex2 softmax, P in registers,
// __launch_bounds__(128,4): regs capped at 128 -> 4 CTAs/SM (was reg-limited
// to 3 at 138 regs).
// ---------------------------------------------------------------------------

#define Tn    2048
#define Bn    2
#define Dn    256
#define Mrows 4096
#define NSPLIT 8

// fp32 scratch
__device__ float g_x[Mrows * Dn];
__device__ float g_tmp[Mrows * Dn];

// attention split-KV partials
__device__ float g_attp[NSPLIT][Mrows * Dn];
__device__ float g_pm[NSPLIT][Mrows * 4];
__device__ float g_pl[NSPLIT][Mrows * 4];

// bf16 hi/lo activations, qkv, MLP hidden
__device__ __nv_bfloat16 g_acth[Mrows * Dn],  g_actl[Mrows * Dn];
__device__ __nv_bfloat16 g_qkvh[Mrows * 768], g_qkvl[Mrows * 768];
__device__ __nv_bfloat16 g_hh[Mrows * 1024],  g_hl[Mrows * 1024];

// bf16 hi/lo weights
__device__ __nv_bfloat16 g_wqkv_h[4 * 768 * 256],  g_wqkv_l[4 * 768 * 256];
__device__ __nv_bfloat16 g_wfc_h [4 * 256 * 256],  g_wfc_l [4 * 256 * 256];
__device__ __nv_bfloat16 g_w1_h  [4 * 1024 * 256], g_w1_l  [4 * 1024 * 256];
__device__ __nv_bfloat16 g_w2_h  [4 * 256 * 1024], g_w2_l  [4 * 256 * 1024];
__device__ __nv_bfloat16 g_wout_h[32000 * 256],    g_wout_l[32000 * 256];

// ---------------------------------------------------------------------------
// PTX helpers
// ---------------------------------------------------------------------------
__device__ __forceinline__ uint32_t smem_to_u32(const void* p) {
    uint32_t a;
    asm("{ .reg .u64 t; cvta.to.shared.u64 t, %1; cvt.u32.u64 %0, t; }"
        : "=r"(a) : "l"(p));
    return a;
}
__device__ __forceinline__ void ldsm4(uint32_t* r, uint32_t addr) {
    asm volatile("ldmatrix.sync.aligned.m8n8.x4.shared.b16 {%0,%1,%2,%3}, [%4];"
                 : "=r"(r[0]), "=r"(r[1]), "=r"(r[2]), "=r"(r[3]) : "r"(addr));
}
__device__ __forceinline__ void ldsm4t(uint32_t* r, uint32_t addr) {
    asm volatile("ldmatrix.sync.aligned.m8n8.x4.trans.shared.b16 {%0,%1,%2,%3}, [%4];"
                 : "=r"(r[0]), "=r"(r[1]), "=r"(r[2]), "=r"(r[3]) : "r"(addr));
}
__device__ __forceinline__ void mma16816(float* d, const uint32_t* a,
                                         uint32_t b0, uint32_t b1) {
    asm volatile(
        "mma.sync.aligned.m16n8k16.row.col.f32.bf16.bf16.f32 "
        "{%0,%1,%2,%3}, {%4,%5,%6,%7}, {%8,%9}, {%0,%1,%2,%3};"
        : "+f"(d[0]), "+f"(d[1]), "+f"(d[2]), "+f"(d[3])
        : "r"(a[0]), "r"(a[1]), "r"(a[2]), "r"(a[3]), "r"(b0), "r"(b1));
}
__device__ __forceinline__ float ex2f(float x) {
    float y;
    asm("ex2.approx.f32 %0, %1;" : "=f"(y) : "f"(x));
    return y;
}
#define CP_ASYNC16(dst, src) \
    asm volatile("cp.async.cg.shared.global [%0], [%1], 16;" \
                 :: "r"(dst), "l"(src) : "memory")
#define CP_COMMIT()  asm volatile("cp.async.commit_group;" ::: "memory")
#define CP_WAIT0()   asm volatile("cp.async.wait_group 0;" ::: "memory")

__device__ __forceinline__ void split1(float v, __nv_bfloat16& h, __nv_bfloat16& l) {
    h = __float2bfloat16(v);
    l = __float2bfloat16(v - __bfloat162float(h));
}
__device__ __forceinline__ uint32_t pack2(__nv_bfloat16 a, __nv_bfloat16 b) {
    __nv_bfloat162 t(a, b);
    return *(uint32_t*)&t;
}

// ---------------------------------------------------------------------------
// Fused weight split
// ---------------------------------------------------------------------------
__global__ void split_weights(const float* __restrict__ qkv_w,
                              const float* __restrict__ fc_w,
                              const float* __restrict__ w1,
                              const float* __restrict__ w2,
                              const float* __restrict__ out_w)
{
    const int c0 = 196608, c1 = c0 + 65536, c2 = c1 + 262144,
              c3 = c2 + 262144, c4 = c3 + 2048000;
    int stride = gridDim.x * blockDim.x;
    for (int idx = blockIdx.x * blockDim.x + threadIdx.x; idx < c4; idx += stride) {
        const float* src; __nv_bfloat16 *dh, *dl; int li;
        if (idx < c0)      { src = qkv_w; dh = g_wqkv_h; dl = g_wqkv_l; li = idx; }
        else if (idx < c1) { src = fc_w;  dh = g_wfc_h;  dl = g_wfc_l;  li = idx - c0; }
        else if (idx < c2) { src = w1;    dh = g_w1_h;   dl = g_w1_l;   li = idx - c1; }
        else if (idx < c3) { src = w2;    dh = g_w2_h;   dl = g_w2_l;   li = idx - c2; }
        else               { src = out_w; dh = g_wout_h; dl = g_wout_l; li = idx - c3; }
        float4 v = ((const float4*)src)[li];
        __nv_bfloat16 h0, h1, h2, h3, l0, l1, l2, l3;
        split1(v.x, h0, l0); split1(v.y, h1, l1);
        split1(v.z, h2, l2); split1(v.w, h3, l3);
        ((__nv_bfloat162*)dh)[li * 2 + 0] = __nv_bfloat162(h0, h1);
        ((__nv_bfloat162*)dh)[li * 2 + 1] = __nv_bfloat162(h2, h3);
        ((__nv_bfloat162*)dl)[li * 2 + 0] = __nv_bfloat162(l0, l1);
        ((__nv_bfloat162*)dl)[li * 2 + 1] = __nv_bfloat162(l2, l3);
    }
}

// ---------------------------------------------------------------------------
// mma.sync bf16x3 GEMM. TM in {64, 32}, TN = 128. (unchanged)
// ---------------------------------------------------------------------------
#define GSMEM64  (2 * 49152)
#define GSMEM32  (2 * 40960)

template<int TM, int N, int K, int RELU, int WSPLIT>
__device__ __forceinline__ void gemm_body(
    const __nv_bfloat16* __restrict__ Ah, const __nv_bfloat16* __restrict__ Al,
    const __nv_bfloat16* __restrict__ Bh, const __nv_bfloat16* __restrict__ Bl,
    const float* __restrict__ bias, float* __restrict__ C,
    __nv_bfloat16* __restrict__ Ch, __nv_bfloat16* __restrict__ Cl)
{
    extern __shared__ char smem[];
    const uint32_t sb = smem_to_u32(smem);
    const int tid  = threadIdx.x;
    const int wid  = tid >> 5;
    const int lane = tid & 31;
    const int m0   = blockIdx.y * TM;
    const int n0   = blockIdx.x << 7;
    constexpr int NST   = K / 64;
    constexpr int STAGE = (TM == 64) ? 49152 : 40960;
    constexpr int AOFF  = (TM == 64) ? 8192 : 4096;
    constexpr int BOFF  = (TM == 64) ? 16384 : 8192;
    constexpr int BSZ   = 16384;
    const int wr = (TM == 64) ? (wid & 1) : 0;
    const int wc = (TM == 64) ? (wid >> 1) : wid;

    float acc[2][4][4];
#pragma unroll
    for (int i = 0; i < 2; i++)
#pragma unroll
        for (int j = 0; j < 4; j++)
#pragma unroll
            for (int q = 0; q < 4; q++) acc[i][j][q] = 0.f;

    const int q = tid >> 3;
    uint32_t cbyte = (uint32_t)((tid & 7) << 4);
    const uint32_t swq = cbyte ^ (uint32_t)((q & 7) << 4);
    const uint32_t dq  = (uint32_t)q;
    const int ce = (tid & 7) << 3;
    const __nv_bfloat16* pah = Ah + (long)(m0 + q) * K + ce;
    const __nv_bfloat16* pal = Al + (long)(m0 + q) * K + ce;
    const __nv_bfloat16* pbh = Bh + (long)(n0 + q) * K + ce;
    const __nv_bfloat16* pbl = Bl + (long)(n0 + q) * K + ce;
    constexpr int RSTRIDE = (TM == 64) ? 32 : 16;
    constexpr int AU = 2;
    constexpr int BU = (TM == 64) ? 4 : 8;

#define LOAD_STAGE(sbuf, koff)                                                  \
    do {                                                                        \
        uint32_t base = sb + (sbuf) * (uint32_t)STAGE;                          \
        _Pragma("unroll")                                                       \
        for (int u = 0; u < AU; u++) {                                          \
            uint32_t row = dq + u * RSTRIDE;                                    \
            CP_ASYNC16(base + row * 128 + swq,                                  \
                       (const char*)(pah + (long)u * RSTRIDE * K + (koff)));    \
            CP_ASYNC16(base + AOFF + row * 128 + swq,                           \
                       (const char*)(pal + (long)u * RSTRIDE * K + (koff)));    \
        }                                                                       \
        _Pragma("unroll")                                                       \
        for (int u = 0; u < BU; u++) {                                          \
            uint32_t row = dq + u * RSTRIDE;                                    \
            CP_ASYNC16(base + BOFF + row * 128 + swq,                           \
                       (const char*)(pbh + (long)u * RSTRIDE * K + (koff)));    \
            CP_ASYNC16(base + BOFF + BSZ + row * 128 + swq,                     \
                       (const char*)(pbl + (long)u * RSTRIDE * K + (koff)));    \
        }                                                                       \
        CP_COMMIT();                                                            \
    } while (0)

    LOAD_STAGE(0, 0);

    for (int s = 0; s < NST; s++) {
        CP_WAIT0();
        __syncthreads();
        if (s + 1 < NST) LOAD_STAGE((s + 1) & 1, (s + 1) * 64);
        const uint32_t bufb = sb + (uint32_t)((s & 1) * STAGE);

#pragma unroll
        for (int ko = 0; ko < 64; ko += 16) {
            uint32_t afr[2][2][4];
            uint32_t bfr[2][2][4];
            {
                const int rowb = wr * 32 + (lane & 15);
                const int cb   = ko * 2 + ((lane >> 4) << 4);
#pragma unroll
                for (int t = 0; t < 2; t++)
#pragma unroll
                    for (int mi = 0; mi < 2; mi++) {
                        int row = rowb + mi * 16;
                        uint32_t addr = bufb + (uint32_t)(t * AOFF) + row * 128
                                      + (uint32_t)(cb ^ ((row & 7) << 4));
                        ldsm4(afr[t][mi], addr);
                    }
            }
            {
                const int rowb = wc * 32 + (lane & 7) + ((lane >> 4) << 3);
                const int cb   = ko * 2 + (((lane >> 3) & 1) << 4);
#pragma unroll
                for (int t = 0; t < 2; t++)
#pragma unroll
                    for (int nj = 0; nj < 2; nj++) {
                        int row = rowb + nj * 16;
                        uint32_t addr = bufb + (uint32_t)BOFF + (uint32_t)(t * BSZ)
                                      + row * 128 + (uint32_t)(cb ^ ((row & 7) << 4));
                        ldsm4(bfr[t][nj], addr);
                    }
            }
#pragma unroll
            for (int mi = 0; mi < 2; mi++)
#pragma unroll
                for (int nj = 0; nj < 2; nj++)
#pragma unroll
                    for (int hh = 0; hh < 2; hh++) {
                        const int nc = nj * 2 + hh;
                        const uint32_t bh0 = bfr[0][nj][hh * 2];
                        const uint32_t bh1 = bfr[0][nj][hh * 2 + 1];
                        const uint32_t bl0 = bfr[1][nj][hh * 2];
                        const uint32_t bl1 = bfr[1][nj][hh * 2 + 1];
                        mma16816(acc[mi][nc], afr[0][mi], bh0, bh1);
                        mma16816(acc[mi][nc], afr[0][mi], bl0, bl1);
                        mma16816(acc[mi][nc], afr[1][mi], bh0, bh1);
                    }
        }
        __syncthreads();
    }
#undef LOAD_STAGE

#pragma unroll
    for (int mi = 0; mi < 2; mi++)
#pragma unroll
        for (int nc = 0; nc < 4; nc++) {
            int row = m0 + wr * 32 + mi * 16 + (lane >> 2);
            int col = n0 + wc * 32 + nc * 8 + (lane & 3) * 2;
            float b0v = bias[col], b1v = bias[col + 1];
            float v0 = acc[mi][nc][0] + b0v;
            float v1 = acc[mi][nc][1] + b1v;
            float v2 = acc[mi][nc][2] + b0v;
            float v3 = acc[mi][nc][3] + b1v;
            if (RELU) {
                v0 = fmaxf(v0, 0.f); v1 = fmaxf(v1, 0.f);
                v2 = fmaxf(v2, 0.f); v3 = fmaxf(v3, 0.f);
            }
            if (WSPLIT) {
                __nv_bfloat16 h0, h1, h2, h3, l0, l1, l2, l3;
                split1(v0, h0, l0); split1(v1, h1, l1);
                split1(v2, h2, l2); split1(v3, h3, l3);
                *(__nv_bfloat162*)(Ch + (long)row * N + col)       = __nv_bfloat162(h0, h1);
                *(__nv_bfloat162*)(Ch + (long)(row + 8) * N + col) = __nv_bfloat162(h2, h3);
                *(__nv_bfloat162*)(Cl + (long)row * N + col)       = __nv_bfloat162(l0, l1);
                *(__nv_bfloat162*)(Cl + (long)(row + 8) * N + col) = __nv_bfloat162(l2, l3);
            } else {
                *(float2*)(C + (long)row * N + col)       = make_float2(v0, v1);
                *(float2*)(C + (long)(row + 8) * N + col) = make_float2(v2, v3);
            }
        }
}

__global__ __launch_bounds__(256) void gemm_qkv_tc(int l, const float* bias)
{ gemm_body<64, 768, 256, 0, 1>(g_acth, g_actl, g_wqkv_h + l*196608, g_wqkv_l + l*196608,
                                bias, nullptr, g_qkvh, g_qkvl); }
__global__ __launch_bounds__(128) void gemm_fc_tc(int l, const float* bias)
{ gemm_body<32, 256, 256, 0, 0>(g_acth, g_actl, g_wfc_h + l*65536, g_wfc_l + l*65536,
                                bias, g_tmp, nullptr, nullptr); }
__global__ __launch_bounds__(256) void gemm_w1_tc(int l, const float* bias)
{ gemm_body<64, 1024, 256, 1, 1>(g_acth, g_actl, g_w1_h + l*262144, g_w1_l + l*262144,
                                 bias, nullptr, g_hh, g_hl); }
__global__ __launch_bounds__(128) void gemm_w2_tc(int l, const float* bias)
{ gemm_body<32, 256, 1024, 0, 0>(g_hh, g_hl, g_w2_h + l*262144, g_w2_l + l*262144,
                                 bias, g_tmp, nullptr, nullptr); }
__global__ __launch_bounds__(256) void gemm_logits_tc(const float* bias, float* out)
{ gemm_body<64, 32000, 256, 0, 0>(g_acth, g_actl, g_wout_h, g_wout_l,
                                  bias, out, nullptr, nullptr); }

// ---------------------------------------------------------------------------
// Embedding + positional encoding
// ---------------------------------------------------------------------------
__global__ void embed_pos_kernel(const int* __restrict__ tok,
                                 const float* __restrict__ emb)
{
    int row = blockIdx.x;
    int d   = threadIdx.x;
    int t   = row & (Tn - 1);
    int token = tok[row];
    double div = exp(-(double)(d & ~1) * (9.210340371976184 / 256.0));
    double ang = (double)t * div;
    float  pe  = (d & 1) ? (float)cos(ang) : (float)sin(ang);
    float v = emb[token * Dn + d] + pe;
    g_x[row * Dn + d] = v;
    __nv_bfloat16 h, l;
    split1(v, h, l);
    g_acth[row * Dn + d] = h;
    g_actl[row * Dn + d] = l;
}

// ---------------------------------------------------------------------------
// HMMA flash attention, split-KV x8, MUFU ex2 softmax, P in registers.
// __launch_bounds__(128, 4): cap regs at 128 -> 4 CTAs/SM.
// smem 48KB: QH 0 | QL 8K | KH 16K | KL 24K | VH 32K | VL 40K.
// ---------------------------------------------------------------------------
#define AQ_H  0
#define AQ_L  8192
#define AK_H  16384
#define AK_L  24576
#define AV_H  32768
#define AV_L  40960
#define ASMEM 49152
#define QSCALE 0.18033688f    /* 0.125 * log2(e) */

__global__ __launch_bounds__(128, 4) void attn_kernel()
{
    extern __shared__ char smem[];
    const uint32_t sb = smem_to_u32(smem);
    const int tid  = threadIdx.x;
    const int lane = tid & 31;
    const int w    = tid >> 5;
    const int qt   = blockIdx.x;
    const int b    = blockIdx.y >> 2;
    const int h    = blockIdx.y & 3;
    const int half = blockIdx.z;
    const int q0   = qt << 6;

    const int nst = (qt >= half) ? ((qt - half) / NSPLIT + 1) : 0;
    if (nst == 0) return;

    const __nv_bfloat16* bh_ = g_qkvh + (long)b * Tn * 768 + h * 64;
    const __nv_bfloat16* bl_ = g_qkvl + (long)b * Tn * 768 + h * 64;

    const int lr  = tid & 63;
    const int cb0 = (tid >> 6) * 4;

    {
        const __nv_bfloat16* qh = bh_ + (long)(q0 + lr) * 768;
        const __nv_bfloat16* ql = bl_ + (long)(q0 + lr) * 768;
#pragma unroll
        for (int c = cb0; c < cb0 + 4; c++) {
            uint32_t off = (uint32_t)(lr * 128) + (uint32_t)((c * 16) ^ ((lr & 7) << 4));
            CP_ASYNC16(sb + AQ_H + off, qh + c * 8);
            CP_ASYNC16(sb + AQ_L + off, ql + c * 8);
        }
        CP_COMMIT();
    }

    float m_i[2] = {-1e30f, -1e30f};
    float l_i[2] = {0.f, 0.f};
    float oacc[8][4];
#pragma unroll
    for (int j = 0; j < 8; j++)
#pragma unroll
        for (int q = 0; q < 4; q++) oacc[j][q] = 0.f;

    for (int s = 0; s < nst; s++) {
        const int kt = half + NSPLIT * s;
        const int k0 = kt << 6;
        __syncthreads();
        {
            const __nv_bfloat16* kh = bh_ + (long)(k0 + lr) * 768 + 256;
            const __nv_bfloat16* kl = bl_ + (long)(k0 + lr) * 768 + 256;
            const __nv_bfloat16* vh = bh_ + (long)(k0 + lr) * 768 + 512;
            const __nv_bfloat16* vl = bl_ + (long)(k0 + lr) * 768 + 512;
#pragma unroll
            for (int c = cb0; c < cb0 + 4; c++) {
                uint32_t off = (uint32_t)(lr * 128)
                             + (uint32_t)((c * 16) ^ ((lr & 7) << 4));
                CP_ASYNC16(sb + AK_H + off, kh + c * 8);
                CP_ASYNC16(sb + AK_L + off, kl + c * 8);
                CP_ASYNC16(sb + AV_H + off, vh + c * 8);
                CP_ASYNC16(sb + AV_L + off, vl + c * 8);
            }
            CP_COMMIT();
        }
        CP_WAIT0();
        __syncthreads();

        float sacc[8][4];
#pragma unroll
        for (int j = 0; j < 8; j++)
#pragma unroll
            for (int q = 0; q < 4; q++) sacc[j][q] = 0.f;

#pragma unroll
        for (int ko4 = 0; ko4 < 4; ko4++) {
            uint32_t ah[4], al[4];
            {
                int arow = w * 16 + (lane & 15);
                uint32_t acb = (uint32_t)(ko4 * 32 + ((lane >> 4) << 4));
                uint32_t aoff = (uint32_t)(arow * 128) + (acb ^ ((uint32_t)(arow & 7) << 4));
                ldsm4(ah, sb + AQ_H + aoff);
                ldsm4(al, sb + AQ_L + aoff);
            }
#pragma unroll
            for (int nj = 0; nj < 4; nj++) {
                int brow = nj * 16 + (lane & 7) + ((lane >> 4) << 3);
                uint32_t bcb = (uint32_t)(ko4 * 32 + (((lane >> 3) & 1) << 4));
                uint32_t boff = (uint32_t)(brow * 128) + (bcb ^ ((uint32_t)(brow & 7) << 4));
                uint32_t bh[4], bl[4];
                ldsm4(bh, sb + AK_H + boff);
                ldsm4(bl, sb + AK_L + boff);
#pragma unroll
                for (int hh = 0; hh < 2; hh++) {
                    const int j = nj * 2 + hh;
                    mma16816(sacc[j], ah, bh[hh*2], bh[hh*2+1]);
                    mma16816(sacc[j], ah, bl[hh*2], bl[hh*2+1]);
                    mma16816(sacc[j], al, bh[hh*2], bh[hh*2+1]);
                }
            }
        }

#pragma unroll
        for (int j = 0; j < 8; j++)
#pragma unroll
            for (int q = 0; q < 4; q++) sacc[j][q] *= QSCALE;

        if (kt == qt) {
            const int r0 = lane >> 2;
            const int c0 = 2 * (lane & 3);
#pragma unroll
            for (int j = 0; j < 8; j++) {
                int c = j * 8 + c0;
                int rowA = w * 16 + r0;
                int rowB = rowA + 8;
                if (c     > rowA) sacc[j][0] = -1e30f;
                if (c + 1 > rowA) sacc[j][1] = -1e30f;
                if (c     > rowB) sacc[j][2] = -1e30f;
                if (c + 1 > rowB) sacc[j][3] = -1e30f;
            }
        }

#pragma unroll
        for (int rr = 0; rr < 2; rr++) {
            float mx = -1e30f;
#pragma unroll
            for (int j = 0; j < 8; j++)
                mx = fmaxf(mx, fmaxf(sacc[j][rr*2], sacc[j][rr*2+1]));
            mx = fmaxf(mx, __shfl_xor_sync(0xffffffffu, mx, 1));
            mx = fmaxf(mx, __shfl_xor_sync(0xffffffffu, mx, 2));
            float mn   = fmaxf(m_i[rr], mx);
            float corr = ex2f(m_i[rr] - mn);
            float rs = 0.f;
#pragma unroll
            for (int j = 0; j < 8; j++) {
                float p0 = ex2f(sacc[j][rr*2]   - mn);
                float p1 = ex2f(sacc[j][rr*2+1] - mn);
                sacc[j][rr*2] = p0; sacc[j][rr*2+1] = p1;
                rs += p0 + p1;
            }
            rs += __shfl_xor_sync(0xffffffffu, rs, 1);
            rs += __shfl_xor_sync(0xffffffffu, rs, 2);
            l_i[rr] = l_i[rr] * corr + rs;
            m_i[rr] = mn;
#pragma unroll
            for (int j = 0; j < 8; j++) {
                oacc[j][rr*2]   *= corr;
                oacc[j][rr*2+1] *= corr;
            }
        }

        // ---- O += P V : P A-frags built directly from sacc (C==A identity) -
#pragma unroll
        for (int ko4 = 0; ko4 < 4; ko4++) {
            uint32_t ph[4], pl[4];
            {
                const int j0 = ko4 * 2, j1 = j0 + 1;
                __nv_bfloat16 h0, l0, h1, l1;
                split1(sacc[j0][0], h0, l0); split1(sacc[j0][1], h1, l1);
                ph[0] = pack2(h0, h1); pl[0] = pack2(l0, l1);
                split1(sacc[j0][2], h0, l0); split1(sacc[j0][3], h1, l1);
                ph[1] = pack2(h0, h1); pl[1] = pack2(l0, l1);
                split1(sacc[j1][0], h0, l0); split1(sacc[j1][1], h1, l1);
                ph[2] = pack2(h0, h1); pl[2] = pack2(l0, l1);
                split1(sacc[j1][2], h0, l0); split1(sacc[j1][3], h1, l1);
                ph[3] = pack2(h0, h1); pl[3] = pack2(l0, l1);
            }
#pragma unroll
            for (int nj = 0; nj < 4; nj++) {
                int brow = ko4 * 16 + (lane & 7) + (((lane >> 3) & 1) << 3);
                uint32_t bcb = (uint32_t)(nj * 32 + ((lane >> 4) << 4));
                uint32_t boff = (uint32_t)(brow * 128) + (bcb ^ ((uint32_t)(brow & 7) << 4));
                uint32_t vh[4], vl[4];
                ldsm4t(vh, sb + AV_H + boff);
                ldsm4t(vl, sb + AV_L + boff);
#pragma unroll
                for (int hh = 0; hh < 2; hh++) {
                    const int j = nj * 2 + hh;
                    mma16816(oacc[j], ph, vh[hh*2], vh[hh*2+1]);
                    mma16816(oacc[j], ph, vl[hh*2], vl[hh*2+1]);
                    mma16816(oacc[j], pl, vh[hh*2], vh[hh*2+1]);
                }
            }
        }
    }

    float* attp = g_attp[half];
#pragma unroll
    for (int rr = 0; rr < 2; rr++) {
        int row  = w * 16 + (lane >> 2) + rr * 8;
        int grow = b * Tn + q0 + row;
        long gbase = (long)grow * Dn + h * 64;
#pragma unroll
        for (int j = 0; j < 8; j++) {
            int c = j * 8 + 2 * (lane & 3);
            *(float2*)(attp + gbase + c) = make_float2(oacc[j][rr*2], oacc[j][rr*2+1]);
        }
        if ((lane & 3) == 0) {
            g_pm[half][grow * 4 + h] = m_i[rr];
            g_pl[half][grow * 4 + h] = l_i[rr];
        }
    }
}

// ---------------------------------------------------------------------------
// Combine split-KV partials -> bf16 hi/lo activations (bounded by qt).
// ---------------------------------------------------------------------------
__global__ void attn_combine()
{
    int idx = blockIdx.x * 256 + threadIdx.x;
    int row = idx >> 6;
    int dq  = (idx & 63) << 2;
    int h   = dq >> 6;
    int qt  = (row & (Tn - 1)) >> 6;
    int np  = (qt < NSPLIT - 1) ? (qt + 1) : NSPLIT;

    float m = -1e30f;
    for (int p = 0; p < np; p++) m = fmaxf(m, g_pm[p][row * 4 + h]);
    float lsum = 0.f;
    float v0 = 0.f, v1 = 0.f, v2 = 0.f, v3 = 0.f;
    long base = (long)row * Dn + dq;
    for (int p = 0; p < np; p++) {
        float c = ex2f(g_pm[p][row * 4 + h] - m);
        lsum = fmaf(g_pl[p][row * 4 + h], c, lsum);
        float4 pv = *(float4*)(g_attp[p] + base);
        v0 = fmaf(pv.x, c, v0);
        v1 = fmaf(pv.y, c, v1);
        v2 = fmaf(pv.z, c, v2);
        v3 = fmaf(pv.w, c, v3);
    }
    float inv = 1.f / lsum;
    v0 *= inv; v1 *= inv; v2 *= inv; v3 *= inv;
    __nv_bfloat16 h0,h1,h2,h3,l0b,l1b,l2b,l3b;
    split1(v0,h0,l0b); split1(v1,h1,l1b); split1(v2,h2,l2b); split1(v3,h3,l3b);
    *(__nv_bfloat162*)(g_acth + base)     = __nv_bfloat162(h0, h1);
    *(__nv_bfloat162*)(g_acth + base + 2) = __nv_bfloat162(h2, h3);
    *(__nv_bfloat162*)(g_actl + base)     = __nv_bfloat162(l0b, l1b);
    *(__nv_bfloat162*)(g_actl + base + 2) = __nv_bfloat162(l2b, l3b);
}

// ---------------------------------------------------------------------------
// LayerNorm: x = LN(x [+ g_tmp]) * sc + bi ; writes x fp32 AND hi/lo bf16.
// ---------------------------------------------------------------------------
template<int ADD>
__device__ __forceinline__ void ln_body(const float* __restrict__ sc,
                                        const float* __restrict__ bi)
{
    int row  = blockIdx.x * 8 + (threadIdx.x >> 5);
    int lane = threadIdx.x & 31;
    const float* pa = g_x + (long)row * Dn + lane * 8;
    float v[8];
    {
        float4 v0 = *(const float4*)pa;
        float4 v1 = *(const float4*)(pa + 4);
        v[0] = v0.x; v[1] = v0.y; v[2] = v0.z; v[3] = v0.w;
        v[4] = v1.x; v[5] = v1.y; v[6] = v1.z; v[7] = v1.w;
    }
    if (ADD) {
        const float* pr = g_tmp + (long)row * Dn + lane * 8;
        float4 r0 = *(const float4*)pr;
        float4 r1 = *(const float4*)(pr + 4);
        v[0] += r0.x; v[1] += r0.y; v[2] += r0.z; v[3] += r0.w;
        v[4] += r1.x; v[5] += r1.y; v[6] += r1.z; v[7] += r1.w;
    }
    float s = 0.f;
#pragma unroll
    for (int k = 0; k < 8; k++) s += v[k];
#pragma unroll
    for (int ofs = 16; ofs; ofs >>= 1) s += __shfl_xor_sync(0xffffffffu, s, ofs);
    float mu = s * (1.f / 256.f);
    float var = 0.f;
#pragma unroll
    for (int k = 0; k < 8; k++) { float d = v[k] - mu; var = fmaf(d, d, var); }
#pragma unroll
    for (int ofs = 16; ofs; ofs >>= 1) var += __shfl_xor_sync(0xffffffffu, var, ofs);
    float rstd = rsqrtf(var * (1.f / 256.f) + 1e-5f);

    float4 s0 = *(const float4*)(sc + lane * 8);
    float4 s1 = *(const float4*)(sc + lane * 8 + 4);
    float4 b0 = *(const float4*)(bi + lane * 8);
    float4 b1 = *(const float4*)(bi + lane * 8 + 4);
    float scv[8] = {s0.x, s0.y, s0.z, s0.w, s1.x, s1.y, s1.z, s1.w};
    float biv[8] = {b0.x, b0.y, b0.z, b0.w, b1.x, b1.y, b1.z, b1.w};
    float o[8];
    __nv_bfloat16 oh[8], ol[8];
#pragma unroll
    for (int k = 0; k < 8; k++) {
        o[k] = fmaf((v[k] - mu) * rstd, scv[k], biv[k]);
        split1(o[k], oh[k], ol[k]);
    }
    long base = (long)row * Dn + lane * 8;
    *(float4*)(g_x + base)     = make_float4(o[0], o[1], o[2], o[3]);
    *(float4*)(g_x + base + 4) = make_float4(o[4], o[5], o[6], o[7]);
#pragma unroll
    for (int k = 0; k < 4; k++) {
        ((__nv_bfloat162*)(g_acth + base))[k] = __nv_bfloat162(oh[2*k], oh[2*k+1]);
        ((__nv_bfloat162*)(g_actl + base))[k] = __nv_bfloat162(ol[2*k], ol[2*k+1]);
    }
}
__global__ void add_ln_kernel(const float* sc, const float* bi) { ln_body<1>(sc, bi); }
__global__ void final_ln_kernel(const float* sc, const float* bi) { ln_body<0>(sc, bi); }

// ---------------------------------------------------------------------------
// Orchestration
// ---------------------------------------------------------------------------
extern "C" void kernel_launch(void* const* d_in, const int* in_sizes, int n_in,
                              void* d_out, int out_size)
{
    const int*   tokens = (const int*)d_in[0];
    const float* embedw = (const float*)d_in[1];
    const float* qkv_w  = (const float*)d_in[2];
    const float* qkv_b  = (const float*)d_in[3];
    const float* fc_w   = (const float*)d_in[4];
    const float* fc_b   = (const float*)d_in[5];
    const float* ln1_s  = (const float*)d_in[6];
    const float* ln1_b  = (const float*)d_in[7];
    const float* w1     = (const float*)d_in[8];
    const float* b1     = (const float*)d_in[9];
    const float* w2     = (const float*)d_in[10];
    const float* b2     = (const float*)d_in[11];
    const float* ln2_s  = (const float*)d_in[12];
    const float* ln2_b  = (const float*)d_in[13];
    const float* lnf_s  = (const float*)d_in[14];
    const float* lnf_b  = (const float*)d_in[15];
    const float* out_w  = (const float*)d_in[16];
    const float* out_b  = (const float*)d_in[17];
    float* logits = (float*)d_out;

    cudaFuncSetAttribute((const void*)gemm_qkv_tc,
        cudaFuncAttributeMaxDynamicSharedMemorySize, GSMEM64);
    cudaFuncSetAttribute((const void*)gemm_fc_tc,
        cudaFuncAttributeMaxDynamicSharedMemorySize, GSMEM32);
    cudaFuncSetAttribute((const void*)gemm_w1_tc,
        cudaFuncAttributeMaxDynamicSharedMemorySize, GSMEM64);
    cudaFuncSetAttribute((const void*)gemm_w2_tc,
        cudaFuncAttributeMaxDynamicSharedMemorySize, GSMEM32);
    cudaFuncSetAttribute((const void*)gemm_logits_tc,
        cudaFuncAttributeMaxDynamicSharedMemorySize, GSMEM64);
    cudaFuncSetAttribute((const void*)attn_kernel,
        cudaFuncAttributeMaxDynamicSharedMemorySize, ASMEM);

    split_weights<<<2048, 256>>>(qkv_w, fc_w, w1, w2, out_w);
    embed_pos_kernel<<<Mrows, Dn>>>(tokens, embedw);

    for (int l = 0; l < 4; l++) {
        gemm_qkv_tc<<<dim3(6, 64), 256, GSMEM64>>>(l, qkv_b + l * 768);
        attn_kernel<<<dim3(32, Bn * 4, NSPLIT), 128, ASMEM>>>();
        attn_combine<<<1024, 256>>>();
        gemm_fc_tc<<<dim3(2, 128), 128, GSMEM32>>>(l, fc_b + l * 256);
        add_ln_kernel<<<Mrows / 8, 256>>>(ln1_s + l * 256, ln1_b + l * 256);
        gemm_w1_tc<<<dim3(8, 64), 256, GSMEM64>>>(l, b1 + l * 1024);
        gemm_w2_tc<<<dim3(2, 128), 128, GSMEM32>>>(l, b2 + l * 256);
        add_ln_kernel<<<Mrows / 8, 256>>>(ln2_s + l * 256, ln2_b + l * 256);
    }
    final_ln_kernel<<<Mrows / 8, 256>>>(lnf_s, lnf_b);
    gemm_logits_tc<<<dim3(250, 64), 256, GSMEM64>>>(out_b, logits);
}